// round 2
// baseline (speedup 1.0000x reference)
#include <cuda_runtime.h>

#define BTOT 256
#define NTOK 197
#define CIN 384
#define COUT 1152
#define NEXP 4
#define TT 8
#define BB 32
#define KW 3
#define OUT_BT_STRIDE (COUT * NTOK)   // 226944

__device__ float g_rf[BB * NEXP];
__device__ float g_r[BTOT * COUT];    // r[bt][o], includes +1 and mixed bias

// ---------------------------------------------------------------------------
// Kernel 1: rf[b][e] = mean_t(cls) @ rf_w^T + rf_b
// ---------------------------------------------------------------------------
__global__ void k_rf(const float* __restrict__ x, const float* __restrict__ rf_w,
                     const float* __restrict__ rf_b) {
    const int b = blockIdx.x;
    const int tid = threadIdx.x;
    float a0 = 0.f, a1 = 0.f, a2 = 0.f, a3 = 0.f;
    for (int c = tid; c < CIN; c += 128) {
        float p = 0.f;
        #pragma unroll
        for (int t = 0; t < TT; ++t)
            p += x[(size_t)(b * TT + t) * NTOK * CIN + c];
        p *= 0.125f;
        a0 += p * rf_w[0 * CIN + c];
        a1 += p * rf_w[1 * CIN + c];
        a2 += p * rf_w[2 * CIN + c];
        a3 += p * rf_w[3 * CIN + c];
    }
    __shared__ float red[NEXP][128];
    red[0][tid] = a0; red[1][tid] = a1; red[2][tid] = a2; red[3][tid] = a3;
    __syncthreads();
    for (int s = 64; s > 0; s >>= 1) {
        if (tid < s) {
            red[0][tid] += red[0][tid + s];
            red[1][tid] += red[1][tid + s];
            red[2][tid] += red[2][tid + s];
            red[3][tid] += red[3][tid + s];
        }
        __syncthreads();
    }
    if (tid < NEXP) g_rf[b * NEXP + tid] = red[tid][0] + rf_b[tid];
}

// ---------------------------------------------------------------------------
// Kernel 2: routing -> g_r[bt][o] = conv(mixed expert weights, cls) + mixed bias + 1
// Block = (o-tile of 8, b). One warp per output channel o.
// ---------------------------------------------------------------------------
__global__ void k_routing(const float* __restrict__ x, const float* __restrict__ moe_w,
                          const float* __restrict__ moe_b) {
    const int b = blockIdx.y;
    const int tid = threadIdx.x;
    const int lane = tid & 31;
    const int wid = tid >> 5;

    __shared__ float clsp[CIN * 10];   // padded temporal window, [c][tp], tp in 0..9
    __shared__ float srf[NEXP];
    if (tid < NEXP) srf[tid] = g_rf[b * NEXP + tid];
    for (int t = 0; t < TT; ++t)
        for (int c = tid; c < CIN; c += 256)
            clsp[c * 10 + t + 1] = x[(size_t)(b * TT + t) * NTOK * CIN + c];
    for (int c = tid; c < CIN; c += 256) {
        clsp[c * 10 + 0] = 0.f;
        clsp[c * 10 + 9] = 0.f;
    }
    __syncthreads();

    const int o = blockIdx.x * 8 + wid;
    const float rf0 = srf[0], rf1 = srf[1], rf2 = srf[2], rf3 = srf[3];
    float acc[TT];
    #pragma unroll
    for (int t = 0; t < TT; ++t) acc[t] = 0.f;

    const size_t estride = (size_t)COUT * CIN * KW;
    #pragma unroll 1
    for (int ci = 0; ci < 12; ++ci) {
        const int c = ci * 32 + lane;
        const float* wp = moe_w + ((size_t)o * CIN + c) * KW;
        float wv0 = rf0 * wp[0], wv1 = rf0 * wp[1], wv2 = rf0 * wp[2];
        wp += estride;
        wv0 += rf1 * wp[0]; wv1 += rf1 * wp[1]; wv2 += rf1 * wp[2];
        wp += estride;
        wv0 += rf2 * wp[0]; wv1 += rf2 * wp[1]; wv2 += rf2 * wp[2];
        wp += estride;
        wv0 += rf3 * wp[0]; wv1 += rf3 * wp[1]; wv2 += rf3 * wp[2];
        const float* cl = &clsp[c * 10];
        #pragma unroll
        for (int t = 0; t < TT; ++t)
            acc[t] += wv0 * cl[t] + wv1 * cl[t + 1] + wv2 * cl[t + 2];
    }

    #pragma unroll
    for (int off = 16; off; off >>= 1) {
        #pragma unroll
        for (int t = 0; t < TT; ++t)
            acc[t] += __shfl_xor_sync(0xffffffffu, acc[t], off);
    }
    if (lane == 0) {
        float bo = 1.0f;
        #pragma unroll
        for (int e = 0; e < NEXP; ++e) bo += srf[e] * moe_b[e * COUT + o];
        #pragma unroll
        for (int t = 0; t < TT; ++t)
            g_r[(size_t)(b * TT + t) * COUT + o] = acc[t] + bo;
    }
}

// ---------------------------------------------------------------------------
// Kernel 3: main fused GEMM.
// out[bt, o, n] = sum_c (weight[o,c] * r[bt, s*384+c]) * x[bt,n,c] + bias[o]*r[bt,o]
// Viewed as GEMM with rows m = bt*197+n (M=50432), cols o (per 128-o tile, single
// branch s), K=384. A = x scaled by r on load. f32x2 packed FMA microkernel.
// ---------------------------------------------------------------------------
__device__ __forceinline__ unsigned long long pk2(float lo, float hi) {
    unsigned long long r;
    asm("mov.b64 %0, {%1, %2};" : "=l"(r) : "f"(lo), "f"(hi));
    return r;
}
__device__ __forceinline__ void ffma2(unsigned long long& d, unsigned long long a,
                                      unsigned long long b) {
    asm("fma.rn.f32x2 %0, %1, %2, %0;" : "+l"(d) : "l"(a), "l"(b));
}
__device__ __forceinline__ float2 upk2(unsigned long long v) {
    float lo, hi;
    asm("mov.b64 {%0, %1}, %2;" : "=f"(lo), "=f"(hi) : "l"(v));
    return make_float2(lo, hi);
}

__global__ __launch_bounds__(256) void k_main(const float* __restrict__ x,
                                              const float* __restrict__ weight,
                                              const float* __restrict__ bias,
                                              float* __restrict__ out) {
    __shared__ __align__(16) float As[2][16 * 128];
    __shared__ __align__(16) float Bs[2][16 * 128];

    const int tid = threadIdx.x;
    const int oBase = blockIdx.x * 128;
    const int s = blockIdx.x / 3;          // branch (q/k/v)
    const int mBase = blockIdx.y * 128;

    // loader mapping: 256 threads cover 128 rows x 16 k as float4 along k
    const int lr = tid >> 2;               // 0..63
    const int lc = (tid & 3) * 4;          // 0,4,8,12
    const int row0 = mBase + lr;
    const int row1 = row0 + 64;
    const int bt0 = row0 / NTOK;
    const int bt1 = row1 / NTOK;
    const float* xp0 = x + (size_t)row0 * CIN + lc;
    const float* xp1 = x + (size_t)row1 * CIN + lc;
    const float* rp0 = g_r + (size_t)bt0 * COUT + s * CIN + lc;
    const float* rp1 = g_r + (size_t)bt1 * COUT + s * CIN + lc;
    const float* wq0 = weight + (size_t)(oBase + lr) * CIN + lc;
    const float* wq1 = wq0 + (size_t)64 * CIN;

    // microkernel mapping: strided 8-row x 8-col tile
    const int tx = tid & 15;               // row group (rows tx + 16*i)
    const int ty = tid >> 4;               // col group (cols ty*8 .. +7)

    unsigned long long acc[8][4];
    #pragma unroll
    for (int i = 0; i < 8; ++i)
        #pragma unroll
        for (int j = 0; j < 4; ++j) acc[i][j] = 0ULL;

    float4 xa0, xa1, ra0, ra1, wa0, wa1;

    auto ldg = [&](int kb) {
        xa0 = *reinterpret_cast<const float4*>(xp0 + kb);
        xa1 = *reinterpret_cast<const float4*>(xp1 + kb);
        ra0 = *reinterpret_cast<const float4*>(rp0 + kb);
        ra1 = *reinterpret_cast<const float4*>(rp1 + kb);
        wa0 = *reinterpret_cast<const float4*>(wq0 + kb);
        wa1 = *reinterpret_cast<const float4*>(wq1 + kb);
    };
    auto sts = [&](int buf) {
        As[buf][(lc + 0) * 128 + lr] = xa0.x * ra0.x;
        As[buf][(lc + 1) * 128 + lr] = xa0.y * ra0.y;
        As[buf][(lc + 2) * 128 + lr] = xa0.z * ra0.z;
        As[buf][(lc + 3) * 128 + lr] = xa0.w * ra0.w;
        As[buf][(lc + 0) * 128 + lr + 64] = xa1.x * ra1.x;
        As[buf][(lc + 1) * 128 + lr + 64] = xa1.y * ra1.y;
        As[buf][(lc + 2) * 128 + lr + 64] = xa1.z * ra1.z;
        As[buf][(lc + 3) * 128 + lr + 64] = xa1.w * ra1.w;
        Bs[buf][(lc + 0) * 128 + lr] = wa0.x;
        Bs[buf][(lc + 1) * 128 + lr] = wa0.y;
        Bs[buf][(lc + 2) * 128 + lr] = wa0.z;
        Bs[buf][(lc + 3) * 128 + lr] = wa0.w;
        Bs[buf][(lc + 0) * 128 + lr + 64] = wa1.x;
        Bs[buf][(lc + 1) * 128 + lr + 64] = wa1.y;
        Bs[buf][(lc + 2) * 128 + lr + 64] = wa1.z;
        Bs[buf][(lc + 3) * 128 + lr + 64] = wa1.w;
    };

    ldg(0);
    sts(0);
    __syncthreads();

    #pragma unroll 1
    for (int kc = 0; kc < 24; ++kc) {
        const int buf = kc & 1;
        if (kc < 23) ldg((kc + 1) * 16);
        #pragma unroll
        for (int kk = 0; kk < 16; ++kk) {
            float av[8];
            #pragma unroll
            for (int i = 0; i < 8; ++i)
                av[i] = As[buf][kk * 128 + tx + 16 * i];
            const ulonglong2* bq =
                reinterpret_cast<const ulonglong2*>(&Bs[buf][kk * 128 + ty * 8]);
            const ulonglong2 u0 = bq[0];
            const ulonglong2 u1 = bq[1];
            #pragma unroll
            for (int i = 0; i < 8; ++i) {
                const unsigned long long apk = pk2(av[i], av[i]);
                ffma2(acc[i][0], apk, u0.x);
                ffma2(acc[i][1], apk, u0.y);
                ffma2(acc[i][2], apk, u1.x);
                ffma2(acc[i][3], apk, u1.y);
            }
        }
        if (kc < 23) {
            sts(buf ^ 1);
            __syncthreads();
        }
    }

    // epilogue: out[bt, o, n] = acc + bias[o]*r[bt,o]
    float bo[8];
    #pragma unroll
    for (int j = 0; j < 8; ++j) bo[j] = bias[oBase + ty * 8 + j];
    #pragma unroll
    for (int i = 0; i < 8; ++i) {
        const int row = mBase + tx + 16 * i;
        const int bt = row / NTOK;
        const int n = row - bt * NTOK;
        float* op = out + (size_t)bt * OUT_BT_STRIDE + n;
        const float* rrow = g_r + (size_t)bt * COUT + oBase + ty * 8;
        #pragma unroll
        for (int jp = 0; jp < 4; ++jp) {
            const float2 v = upk2(acc[i][jp]);
            const int j0 = jp * 2;
            op[(size_t)(oBase + ty * 8 + j0) * NTOK] = v.x + bo[j0] * rrow[j0];
            op[(size_t)(oBase + ty * 8 + j0 + 1) * NTOK] = v.y + bo[j0 + 1] * rrow[j0 + 1];
        }
    }
}

// ---------------------------------------------------------------------------
extern "C" void kernel_launch(void* const* d_in, const int* in_sizes, int n_in,
                              void* d_out, int out_size) {
    const float* x = (const float*)d_in[0];
    const float* rf_w = (const float*)d_in[1];
    const float* rf_b = (const float*)d_in[2];
    const float* moe_w = (const float*)d_in[3];
    const float* moe_b = (const float*)d_in[4];
    const float* weight = (const float*)d_in[5];
    const float* bias = (const float*)d_in[6];
    float* out = (float*)d_out;

    k_rf<<<32, 128>>>(x, rf_w, rf_b);
    k_routing<<<dim3(144, 32), 256>>>(x, moe_w, moe_b);
    // grid.x = o-tiles (fast dim -> same-m CTAs adjacent for L2 reuse of x rows)
    k_main<<<dim3(9, 394), 256>>>(x, weight, bias, out);
}

// round 4
// speedup vs baseline: 1.4188x; 1.4188x over previous
#include <cuda_runtime.h>
#include <cuda_bf16.h>
#include <cstdint>

#define NTOK 197
#define CIN 384
#define COUT 1152
#define TT 8
#define OUT_BT_STRIDE (COUT * NTOK)

__device__ float g_rf[32 * 4];
__device__ float g_r[256 * COUT];
__device__ uint4 g_wh4[COUT * CIN / 8];   // weight hi bf16, [o][k] row-major
__device__ uint4 g_wl4[COUT * CIN / 8];   // weight lo bf16

// ======================= helpers =======================
__device__ __forceinline__ uint32_t smem_u32(const void* p) {
    uint32_t a;
    asm("{ .reg .u64 t; cvta.to.shared.u64 t, %1; cvt.u32.u64 %0, t; }" : "=r"(a) : "l"(p));
    return a;
}
__device__ __forceinline__ uint32_t bsplit2(float a, float b, uint32_t& lo) {
    __nv_bfloat162 h = __floats2bfloat162_rn(a, b);
    float2 hf = __bfloat1622float2(h);
    __nv_bfloat162 l = __floats2bfloat162_rn(a - hf.x, b - hf.y);
    lo = *reinterpret_cast<uint32_t*>(&l);
    return *reinterpret_cast<uint32_t*>(&h);
}
#define STS128(a, v0, v1, v2, v3) \
    asm volatile("st.shared.v4.b32 [%0], {%1, %2, %3, %4};" :: "r"(a), "r"(v0), "r"(v1), "r"(v2), "r"(v3) : "memory")
#define CP16(dst, src) \
    asm volatile("cp.async.cg.shared.global [%0], [%1], 16;" :: "r"(dst), "l"(src) : "memory")
#define CP_COMMIT() asm volatile("cp.async.commit_group;" ::: "memory")
#define CP_WAIT1() asm volatile("cp.async.wait_group 1;" ::: "memory")
#define CP_WAIT0() asm volatile("cp.async.wait_group 0;" ::: "memory")
#define LDSM4(r, a)                                                                   \
    asm volatile("ldmatrix.sync.aligned.m8n8.x4.shared.b16 {%0,%1,%2,%3}, [%4];"      \
        : "=r"((r)[0]), "=r"((r)[1]), "=r"((r)[2]), "=r"((r)[3]) : "r"(a))
#define MMA16816(d, a, b0, b1)                                                        \
    asm volatile("mma.sync.aligned.m16n8k16.row.col.f32.bf16.bf16.f32 "               \
        "{%0,%1,%2,%3}, {%4,%5,%6,%7}, {%8,%9}, {%0,%1,%2,%3};"                       \
        : "+f"((d)[0]), "+f"((d)[1]), "+f"((d)[2]), "+f"((d)[3])                      \
        : "r"((a)[0]), "r"((a)[1]), "r"((a)[2]), "r"((a)[3]), "r"(b0), "r"(b1))

// ======================= Kernel 0: weight bf16 hi/lo split =======================
__global__ void k_wsplit(const float* __restrict__ w) {
    int i = blockIdx.x * 256 + threadIdx.x;   // uint4 index, 8 weights each
    const float4 v0 = reinterpret_cast<const float4*>(w)[i * 2];
    const float4 v1 = reinterpret_cast<const float4*>(w)[i * 2 + 1];
    uint32_t h[4], l[4];
    h[0] = bsplit2(v0.x, v0.y, l[0]);
    h[1] = bsplit2(v0.z, v0.w, l[1]);
    h[2] = bsplit2(v1.x, v1.y, l[2]);
    h[3] = bsplit2(v1.z, v1.w, l[3]);
    g_wh4[i] = make_uint4(h[0], h[1], h[2], h[3]);
    g_wl4[i] = make_uint4(l[0], l[1], l[2], l[3]);
}

// ======================= Kernel 1: rf =======================
__global__ void k_rf(const float* __restrict__ x, const float* __restrict__ rf_w,
                     const float* __restrict__ rf_b) {
    const int b = blockIdx.x;
    const int tid = threadIdx.x;
    float a0 = 0.f, a1 = 0.f, a2 = 0.f, a3 = 0.f;
    for (int c = tid; c < CIN; c += 128) {
        float p = 0.f;
        #pragma unroll
        for (int t = 0; t < TT; ++t)
            p += x[(size_t)(b * TT + t) * NTOK * CIN + c];
        p *= 0.125f;
        a0 += p * rf_w[0 * CIN + c];
        a1 += p * rf_w[1 * CIN + c];
        a2 += p * rf_w[2 * CIN + c];
        a3 += p * rf_w[3 * CIN + c];
    }
    __shared__ float red[4][128];
    red[0][tid] = a0; red[1][tid] = a1; red[2][tid] = a2; red[3][tid] = a3;
    __syncthreads();
    for (int s = 64; s > 0; s >>= 1) {
        if (tid < s) {
            red[0][tid] += red[0][tid + s];
            red[1][tid] += red[1][tid + s];
            red[2][tid] += red[2][tid + s];
            red[3][tid] += red[3][tid + s];
        }
        __syncthreads();
    }
    if (tid < 4) g_rf[b * 4 + tid] = red[tid][0] + rf_b[tid];
}

// ======================= Kernel 2: routing =======================
__global__ __launch_bounds__(256) void k_routing(const float* __restrict__ x,
                                                 const float* __restrict__ moe_w,
                                                 const float* __restrict__ moe_b) {
    extern __shared__ float rsm[];            // clsp[4][384][10]
    __shared__ float srf[16];
    const int tid = threadIdx.x, lane = tid & 31, wid = tid >> 5;
    const int o = blockIdx.x * 8 + wid;

    #pragma unroll 1
    for (int bg = 0; bg < 8; ++bg) {
        const int b0 = bg * 4;
        __syncthreads();
        if (tid < 16) srf[tid] = g_rf[(b0 + (tid >> 2)) * 4 + (tid & 3)];
        #pragma unroll 1
        for (int it = 0; it < 48; ++it) {
            int e = it * 256 + tid;
            int bi = e / 3072;
            int r2 = e - bi * 3072;
            int t = r2 / CIN;
            int c = r2 - t * CIN;
            rsm[bi * 3840 + c * 10 + t + 1] =
                x[(size_t)((b0 + bi) * TT + t) * NTOK * CIN + c];
        }
        #pragma unroll 1
        for (int it = 0; it < 12; ++it) {
            int e = it * 256 + tid;
            int bi = e / 768;
            int r2 = e - bi * 768;
            int c = r2 >> 1;
            rsm[bi * 3840 + c * 10 + (r2 & 1) * 9] = 0.f;
        }
        __syncthreads();

        float f[16];
        #pragma unroll
        for (int i = 0; i < 16; ++i) f[i] = srf[i];

        float acc[4][8];
        #pragma unroll
        for (int bi = 0; bi < 4; ++bi)
            #pragma unroll
            for (int t = 0; t < TT; ++t) acc[bi][t] = 0.f;

        #pragma unroll 1
        for (int ci = 0; ci < 12; ++ci) {
            const int c = ci * 32 + lane;
            float w[4][3];
            #pragma unroll
            for (int e = 0; e < 4; ++e) {
                const float* wp = moe_w + ((size_t)(e * COUT + o) * CIN + c) * 3;
                w[e][0] = wp[0]; w[e][1] = wp[1]; w[e][2] = wp[2];
            }
            #pragma unroll
            for (int bi = 0; bi < 4; ++bi) {
                const float f0 = f[bi * 4 + 0], f1 = f[bi * 4 + 1];
                const float f2 = f[bi * 4 + 2], f3 = f[bi * 4 + 3];
                const float wv0 = f0 * w[0][0] + f1 * w[1][0] + f2 * w[2][0] + f3 * w[3][0];
                const float wv1 = f0 * w[0][1] + f1 * w[1][1] + f2 * w[2][1] + f3 * w[3][1];
                const float wv2 = f0 * w[0][2] + f1 * w[1][2] + f2 * w[2][2] + f3 * w[3][2];
                const float* cl = rsm + bi * 3840 + c * 10;
                float cv[10];
                #pragma unroll
                for (int t = 0; t < 10; ++t) cv[t] = cl[t];
                #pragma unroll
                for (int t = 0; t < TT; ++t)
                    acc[bi][t] += wv0 * cv[t] + wv1 * cv[t + 1] + wv2 * cv[t + 2];
            }
        }

        float myval = 0.f;
        #pragma unroll
        for (int j = 0; j < 32; ++j) {
            float v = acc[j >> 3][j & 7];
            #pragma unroll
            for (int off = 16; off; off >>= 1) v += __shfl_xor_sync(0xffffffffu, v, off);
            if (lane == j) myval = v;
        }
        {
            const int bi = lane >> 3, t = lane & 7;
            float bo = 1.0f;
            #pragma unroll
            for (int e = 0; e < 4; ++e) bo += f[bi * 4 + e] * moe_b[e * COUT + o];
            g_r[(size_t)((b0 + bi) * TT + t) * COUT + o] = myval + bo;
        }
    }
}

// ======================= Kernel 3: main mma.sync GEMM =======================
// CTA 128m x 128o, K=384 in 6 chunks of 64 bf16 (SW128 rows). Split-bf16 3-pass.
#define STG_STRIDE 65536
#define OFF_AH 0
#define OFF_AL 16384
#define OFF_BH 32768
#define OFF_BL 49152
#define SMEM_MAIN (1024 + 2 * STG_STRIDE)

__global__ __launch_bounds__(256, 1) void k_main(const float* __restrict__ x,
                                                 const float* __restrict__ bias,
                                                 float* __restrict__ out) {
    extern __shared__ char dsm[];
    const uint32_t sb = (smem_u32(dsm) + 1023u) & ~1023u;
    const int tid = threadIdx.x, lane = tid & 31, wid = tid >> 5;
    const int oBase = blockIdx.x * 128;
    const int s = blockIdx.x / 3;
    const int mBase = blockIdx.y * 128;

    // A loader mapping: 2 threads per row, 32 k each
    const int arow = tid >> 1;
    const int ahalf = tid & 1;
    const int am = mBase + arow;
    const int abt = am / NTOK;
    const float* axp = x + (size_t)am * CIN + ahalf * 32;
    const float* arp = g_r + (size_t)abt * COUT + s * CIN + ahalf * 32;

    // warp tile: 4m x 2n warps, each 32m x 64o
    const int wm = (wid & 3) * 32;
    const int wn = (wid >> 2) * 64;

    float acc[2][8][4];
    #pragma unroll
    for (int i = 0; i < 2; ++i)
        #pragma unroll
        for (int j = 0; j < 8; ++j)
            #pragma unroll
            for (int e = 0; e < 4; ++e) acc[i][j][e] = 0.f;

    float4 xr[8];

    auto ldgA = [&](int kOff) {
        const float4* xp4 = reinterpret_cast<const float4*>(axp + kOff);
        #pragma unroll
        for (int i = 0; i < 8; ++i) xr[i] = xp4[i];
    };
    auto stsA = [&](int kOff, int buf) {
        const float4* rp4 = reinterpret_cast<const float4*>(arp + kOff);
        const uint32_t aH = sb + buf * STG_STRIDE + OFF_AH;
        const uint32_t aL = sb + buf * STG_STRIDE + OFF_AL;
        #pragma unroll
        for (int g = 0; g < 4; ++g) {
            const float4 xa = xr[2 * g], xb = xr[2 * g + 1];
            const float4 ra = rp4[2 * g], rb = rp4[2 * g + 1];
            uint32_t h[4], l[4];
            h[0] = bsplit2(xa.x * ra.x, xa.y * ra.y, l[0]);
            h[1] = bsplit2(xa.z * ra.z, xa.w * ra.w, l[1]);
            h[2] = bsplit2(xb.x * rb.x, xb.y * rb.y, l[2]);
            h[3] = bsplit2(xb.z * rb.z, xb.w * rb.w, l[3]);
            const uint32_t off = (uint32_t)(arow * 128 + (ahalf * 32 + g * 8) * 2);
            const uint32_t sw = off ^ ((off >> 3) & 0x70);
            STS128(aH + sw, h[0], h[1], h[2], h[3]);
            STS128(aL + sw, l[0], l[1], l[2], l[3]);
        }
    };
    auto ldB = [&](int kOff, int buf) {
        const uint32_t bH = sb + buf * STG_STRIDE + OFF_BH;
        const uint32_t bL = sb + buf * STG_STRIDE + OFF_BL;
        const char* gh = (const char*)g_wh4;
        const char* gl = (const char*)g_wl4;
        #pragma unroll
        for (int it = 0; it < 4; ++it) {
            const int idx = it * 256 + tid;          // 1024 16B-vectors
            const int ol = idx >> 3;
            const int kq = idx & 7;
            const size_t gb = ((size_t)(oBase + ol) * CIN + kOff + kq * 8) * 2;
            const uint32_t off = (uint32_t)(ol * 128 + kq * 16);
            const uint32_t sw = off ^ ((off >> 3) & 0x70);
            CP16(bH + sw, gh + gb);
            CP16(bL + sw, gl + gb);
        }
    };
    auto compute = [&](int buf) {
        const uint32_t aH = sb + buf * STG_STRIDE + OFF_AH;
        const uint32_t aL = sb + buf * STG_STRIDE + OFF_AL;
        const uint32_t bH = sb + buf * STG_STRIDE + OFF_BH;
        const uint32_t bL = sb + buf * STG_STRIDE + OFF_BL;
        const int lrow = lane & 15, lkh = lane >> 4;
        #pragma unroll
        for (int kk = 0; kk < 4; ++kk) {
            const uint32_t kbyte = kk * 32 + lkh * 16;
            uint32_t Ah[2][4], Al[2][4], Bh[4][4], Bl[4][4];
            #pragma unroll
            for (int mt = 0; mt < 2; ++mt) {
                const uint32_t off = (uint32_t)((wm + mt * 16 + lrow) * 128) + kbyte;
                const uint32_t sw = off ^ ((off >> 3) & 0x70);
                LDSM4(Ah[mt], aH + sw);
                LDSM4(Al[mt], aL + sw);
            }
            #pragma unroll
            for (int nt = 0; nt < 4; ++nt) {
                const uint32_t off = (uint32_t)((wn + nt * 16 + lrow) * 128) + kbyte;
                const uint32_t sw = off ^ ((off >> 3) & 0x70);
                LDSM4(Bh[nt], bH + sw);
                LDSM4(Bl[nt], bL + sw);
            }
            #pragma unroll
            for (int mt = 0; mt < 2; ++mt)
                #pragma unroll
                for (int nt = 0; nt < 4; ++nt) {
                    MMA16816(acc[mt][nt * 2],     Ah[mt], Bh[nt][0], Bh[nt][2]);
                    MMA16816(acc[mt][nt * 2 + 1], Ah[mt], Bh[nt][1], Bh[nt][3]);
                    MMA16816(acc[mt][nt * 2],     Al[mt], Bh[nt][0], Bh[nt][2]);
                    MMA16816(acc[mt][nt * 2 + 1], Al[mt], Bh[nt][1], Bh[nt][3]);
                    MMA16816(acc[mt][nt * 2],     Ah[mt], Bl[nt][0], Bl[nt][2]);
                    MMA16816(acc[mt][nt * 2 + 1], Ah[mt], Bl[nt][1], Bl[nt][3]);
                }
        }
    };

    // ---- prologue ----
    ldgA(0);
    ldB(0, 0); CP_COMMIT();
    stsA(0, 0);
    ldgA(64);
    ldB(64, 1); CP_COMMIT();
    CP_WAIT1();
    __syncthreads();

    // ---- mainloop ----
    #pragma unroll 1
    for (int kc = 0; kc < 6; ++kc) {
        const int buf = kc & 1;
        compute(buf);
        if (kc < 5) {
            __syncthreads();
            stsA((kc + 1) * 64, buf ^ 1);
            if (kc < 4) {
                ldgA((kc + 2) * 64);
                ldB((kc + 2) * 64, buf); CP_COMMIT();
                CP_WAIT1();
            } else {
                CP_WAIT0();
            }
            __syncthreads();
        }
    }

    // ---- epilogue ----
    #pragma unroll
    for (int mt = 0; mt < 2; ++mt)
        #pragma unroll
        for (int rh = 0; rh < 2; ++rh) {
            const int m = mBase + wm + mt * 16 + (lane >> 2) + rh * 8;
            const int bt = m / NTOK;
            const int n = m - bt * NTOK;
            float* op = out + (size_t)bt * OUT_BT_STRIDE + n;
            const float* rr = g_r + (size_t)bt * COUT + oBase + wn;
            const float* bb = bias + oBase + wn;
            #pragma unroll
            for (int nt2 = 0; nt2 < 8; ++nt2) {
                const int c0 = nt2 * 8 + (lane & 3) * 2;
                const float v0 = acc[mt][nt2][rh * 2 + 0] + bb[c0] * rr[c0];
                const float v1 = acc[mt][nt2][rh * 2 + 1] + bb[c0 + 1] * rr[c0 + 1];
                op[(size_t)(oBase + wn + c0) * NTOK] = v0;
                op[(size_t)(oBase + wn + c0 + 1) * NTOK] = v1;
            }
        }
}

// ======================= launch =======================
extern "C" void kernel_launch(void* const* d_in, const int* in_sizes, int n_in,
                              void* d_out, int out_size) {
    const float* x = (const float*)d_in[0];
    const float* rf_w = (const float*)d_in[1];
    const float* rf_b = (const float*)d_in[2];
    const float* moe_w = (const float*)d_in[3];
    const float* moe_b = (const float*)d_in[4];
    const float* weight = (const float*)d_in[5];
    const float* bias = (const float*)d_in[6];
    float* out = (float*)d_out;

    cudaFuncSetAttribute(k_main, cudaFuncAttributeMaxDynamicSharedMemorySize, SMEM_MAIN);
    cudaFuncSetAttribute(k_routing, cudaFuncAttributeMaxDynamicSharedMemorySize, 61440);

    k_rf<<<32, 128>>>(x, rf_w, rf_b);
    k_wsplit<<<216, 256>>>(weight);
    k_routing<<<144, 256, 61440>>>(x, moe_w, moe_b);
    k_main<<<dim3(9, 394), 256, SMEM_MAIN>>>(x, bias, out);
}

// round 6
// speedup vs baseline: 1.6157x; 1.1388x over previous
#include <cuda_runtime.h>
#include <cuda_bf16.h>
#include <cstdint>

#define NTOK 197
#define CIN 384
#define COUT 1152
#define TT 8
#define OUT_BT_STRIDE (COUT * NTOK)

__device__ float g_rf[32 * 4];
__device__ float g_r[256 * COUT];
__device__ uint4 g_wh4[COUT * CIN / 8];   // weight hi bf16, [o][k] row-major
__device__ uint4 g_wl4[COUT * CIN / 8];   // weight lo bf16

// ======================= helpers =======================
__device__ __forceinline__ uint32_t smem_u32(const void* p) {
    uint32_t a;
    asm("{ .reg .u64 t; cvta.to.shared.u64 t, %1; cvt.u32.u64 %0, t; }" : "=r"(a) : "l"(p));
    return a;
}
__device__ __forceinline__ uint32_t bsplit2(float a, float b, uint32_t& lo) {
    __nv_bfloat162 h = __floats2bfloat162_rn(a, b);
    float2 hf = __bfloat1622float2(h);
    __nv_bfloat162 l = __floats2bfloat162_rn(a - hf.x, b - hf.y);
    lo = *reinterpret_cast<uint32_t*>(&l);
    return *reinterpret_cast<uint32_t*>(&h);
}
#define STS128(a, v0, v1, v2, v3) \
    asm volatile("st.shared.v4.b32 [%0], {%1, %2, %3, %4};" :: "r"(a), "r"(v0), "r"(v1), "r"(v2), "r"(v3) : "memory")
#define CP16(dst, src) \
    asm volatile("cp.async.cg.shared.global [%0], [%1], 16;" :: "r"(dst), "l"(src) : "memory")
#define CP_COMMIT() asm volatile("cp.async.commit_group;" ::: "memory")
#define CP_WAIT1() asm volatile("cp.async.wait_group 1;" ::: "memory")
#define CP_WAIT0() asm volatile("cp.async.wait_group 0;" ::: "memory")
#define LDSM4(r, a)                                                                   \
    asm volatile("ldmatrix.sync.aligned.m8n8.x4.shared.b16 {%0,%1,%2,%3}, [%4];"      \
        : "=r"((r)[0]), "=r"((r)[1]), "=r"((r)[2]), "=r"((r)[3]) : "r"(a))
#define MMA16816(d, a, b0, b1)                                                        \
    asm volatile("mma.sync.aligned.m16n8k16.row.col.f32.bf16.bf16.f32 "               \
        "{%0,%1,%2,%3}, {%4,%5,%6,%7}, {%8,%9}, {%0,%1,%2,%3};"                       \
        : "+f"((d)[0]), "+f"((d)[1]), "+f"((d)[2]), "+f"((d)[3])                      \
        : "r"((a)[0]), "r"((a)[1]), "r"((a)[2]), "r"((a)[3]), "r"(b0), "r"(b1))

// ======================= Kernel 0: weight bf16 hi/lo split =======================
__global__ void k_wsplit(const float* __restrict__ w) {
    int i = blockIdx.x * 256 + threadIdx.x;
    const float4 v0 = reinterpret_cast<const float4*>(w)[i * 2];
    const float4 v1 = reinterpret_cast<const float4*>(w)[i * 2 + 1];
    uint32_t h[4], l[4];
    h[0] = bsplit2(v0.x, v0.y, l[0]);
    h[1] = bsplit2(v0.z, v0.w, l[1]);
    h[2] = bsplit2(v1.x, v1.y, l[2]);
    h[3] = bsplit2(v1.z, v1.w, l[3]);
    g_wh4[i] = make_uint4(h[0], h[1], h[2], h[3]);
    g_wl4[i] = make_uint4(l[0], l[1], l[2], l[3]);
}

// ======================= Kernel 1: rf =======================
__global__ void k_rf(const float* __restrict__ x, const float* __restrict__ rf_w,
                     const float* __restrict__ rf_b) {
    const int b = blockIdx.x;
    const int tid = threadIdx.x;
    float a0 = 0.f, a1 = 0.f, a2 = 0.f, a3 = 0.f;
    for (int c = tid; c < CIN; c += 128) {
        float p = 0.f;
        #pragma unroll
        for (int t = 0; t < TT; ++t)
            p += x[(size_t)(b * TT + t) * NTOK * CIN + c];
        p *= 0.125f;
        a0 += p * rf_w[0 * CIN + c];
        a1 += p * rf_w[1 * CIN + c];
        a2 += p * rf_w[2 * CIN + c];
        a3 += p * rf_w[3 * CIN + c];
    }
    __shared__ float red[4][128];
    red[0][tid] = a0; red[1][tid] = a1; red[2][tid] = a2; red[3][tid] = a3;
    __syncthreads();
    for (int s = 64; s > 0; s >>= 1) {
        if (tid < s) {
            red[0][tid] += red[0][tid + s];
            red[1][tid] += red[1][tid + s];
            red[2][tid] += red[2][tid + s];
            red[3][tid] += red[3][tid + s];
        }
        __syncthreads();
    }
    if (tid < 4) g_rf[b * 4 + tid] = red[tid][0] + rf_b[tid];
}

// ======================= Kernel 2: routing =======================
// grid = (144 o-tiles of 8, 8 b-groups of 4). One warp per o. moe_w is 21MB,
// fully L2-resident, so the 8x b-group re-read is nearly free.
__global__ __launch_bounds__(256) void k_routing(const float* __restrict__ x,
                                                 const float* __restrict__ moe_w,
                                                 const float* __restrict__ moe_b) {
    extern __shared__ float rsm[];            // clsp[4][384][10]
    __shared__ float srf[16];
    const int tid = threadIdx.x, lane = tid & 31, wid = tid >> 5;
    const int o = blockIdx.x * 8 + wid;
    const int b0 = blockIdx.y * 4;

    if (tid < 16) srf[tid] = g_rf[(b0 + (tid >> 2)) * 4 + (tid & 3)];
    #pragma unroll 1
    for (int it = 0; it < 48; ++it) {
        int e = it * 256 + tid;               // 4*8*384 = 12288
        int bi = e / 3072;
        int r2 = e - bi * 3072;
        int t = r2 / CIN;
        int c = r2 - t * CIN;
        rsm[bi * 3840 + c * 10 + t + 1] =
            x[(size_t)((b0 + bi) * TT + t) * NTOK * CIN + c];
    }
    #pragma unroll 1
    for (int it = 0; it < 12; ++it) {
        int e = it * 256 + tid;               // 4*384*2 = 3072
        int bi = e / 768;
        int r2 = e - bi * 768;
        int c = r2 >> 1;
        rsm[bi * 3840 + c * 10 + (r2 & 1) * 9] = 0.f;
    }
    __syncthreads();

    float f[16];
    #pragma unroll
    for (int i = 0; i < 16; ++i) f[i] = srf[i];

    float vals[32];
    #pragma unroll
    for (int i = 0; i < 32; ++i) vals[i] = 0.f;

    #pragma unroll 1
    for (int ci = 0; ci < 12; ++ci) {
        const int c = ci * 32 + lane;
        float w[4][3];
        #pragma unroll
        for (int e = 0; e < 4; ++e) {
            const float* wp = moe_w + ((size_t)(e * COUT + o) * CIN + c) * 3;
            w[e][0] = wp[0]; w[e][1] = wp[1]; w[e][2] = wp[2];
        }
        #pragma unroll
        for (int bi = 0; bi < 4; ++bi) {
            const float f0 = f[bi * 4 + 0], f1 = f[bi * 4 + 1];
            const float f2 = f[bi * 4 + 2], f3 = f[bi * 4 + 3];
            const float wv0 = f0 * w[0][0] + f1 * w[1][0] + f2 * w[2][0] + f3 * w[3][0];
            const float wv1 = f0 * w[0][1] + f1 * w[1][1] + f2 * w[2][1] + f3 * w[3][1];
            const float wv2 = f0 * w[0][2] + f1 * w[1][2] + f2 * w[2][2] + f3 * w[3][2];
            const float* cl = rsm + bi * 3840 + c * 10;
            float cv[10];
            #pragma unroll
            for (int t = 0; t < 10; ++t) cv[t] = cl[t];
            #pragma unroll
            for (int t = 0; t < TT; ++t)
                vals[bi * 8 + t] += wv0 * cv[t] + wv1 * cv[t + 1] + wv2 * cv[t + 2];
        }
    }

    // butterfly reduce 32 per-lane values -> lane L holds sum of index L (31 shfls)
    int cnt = 32;
    #pragma unroll
    for (int off = 16; off; off >>= 1) {
        cnt >>= 1;
        #pragma unroll 16
        for (int j = 0; j < cnt; ++j) {
            const float send = (lane & off) ? vals[j] : vals[j + cnt];
            const float other = __shfl_xor_sync(0xffffffffu, send, off);
            vals[j] = ((lane & off) ? vals[j + cnt] : vals[j]) + other;
        }
    }
    {
        const int bi = lane >> 3, t = lane & 7;
        float bo = 1.0f;
        #pragma unroll
        for (int e = 0; e < 4; ++e) bo += f[bi * 4 + e] * moe_b[e * COUT + o];
        g_r[(size_t)((b0 + bi) * TT + t) * COUT + o] = vals[0] + bo;
    }
}

// ======================= Kernel 3: main mma.sync GEMM =======================
// CTA 128m x 128o, K=384 in 6 chunks of 64 bf16 (SW128 rows). Split-bf16 3-pass.
// stsA overlapped ahead of compute; barrier between compute and the cp.async
// refill of the just-read B buffer (fixes the R5 race).
#define STG_STRIDE 65536
#define OFF_AH 0
#define OFF_AL 16384
#define OFF_BH 32768
#define OFF_BL 49152
#define SMEM_MAIN (1024 + 2 * STG_STRIDE)

__global__ __launch_bounds__(256, 1) void k_main(const float* __restrict__ x,
                                                 const float* __restrict__ bias,
                                                 float* __restrict__ out) {
    extern __shared__ char dsm[];
    const uint32_t sb = (smem_u32(dsm) + 1023u) & ~1023u;
    const int tid = threadIdx.x, lane = tid & 31, wid = tid >> 5;
    const int oBase = blockIdx.x * 128;
    const int s = blockIdx.x / 3;
    const int mBase = blockIdx.y * 128;

    // A loader mapping: 2 threads per row, 32 k each
    const int arow = tid >> 1;
    const int ahalf = tid & 1;
    const int am = mBase + arow;
    const int abt = am / NTOK;
    const float* axp = x + (size_t)am * CIN + ahalf * 32;
    const float* arp = g_r + (size_t)abt * COUT + s * CIN + ahalf * 32;

    // hoisted swizzled STS offsets for A (kb = ahalf*64 + g*16 < 128, no carry)
    uint32_t sA[4];
    {
        const uint32_t xm = (uint32_t)(arow & 7) * 16;
        #pragma unroll
        for (int g = 0; g < 4; ++g)
            sA[g] = (uint32_t)arow * 128 + (((uint32_t)(ahalf * 64 + g * 16)) ^ xm);
    }

    // warp tile: 4m x 2n warps, each 32m x 64o
    const int wm = (wid & 3) * 32;
    const int wn = (wid >> 2) * 64;

    // hoisted LDSM bases: addr = bufbase + OFF + base[i] + (kbl ^ xm[i])
    const int lrow = lane & 15, lkh = lane >> 4;
    uint32_t aBase[2], aXm[2], bBase[4], bXm[4];
    #pragma unroll
    for (int mt = 0; mt < 2; ++mt) {
        const int row = wm + mt * 16 + lrow;
        aBase[mt] = (uint32_t)row * 128;
        aXm[mt] = (uint32_t)(row & 7) * 16;
    }
    #pragma unroll
    for (int nt = 0; nt < 4; ++nt) {
        const int row = wn + nt * 16 + lrow;
        bBase[nt] = (uint32_t)row * 128;
        bXm[nt] = (uint32_t)(row & 7) * 16;
    }

    float acc[2][8][4];
    #pragma unroll
    for (int i = 0; i < 2; ++i)
        #pragma unroll
        for (int j = 0; j < 8; ++j)
            #pragma unroll
            for (int e = 0; e < 4; ++e) acc[i][j][e] = 0.f;

    float4 xr[8];

    auto ldgA = [&](int kOff) {
        const float4* xp4 = reinterpret_cast<const float4*>(axp + kOff);
        #pragma unroll
        for (int i = 0; i < 8; ++i) xr[i] = xp4[i];
    };
    auto stsA = [&](int kOff, int buf) {
        const float4* rp4 = reinterpret_cast<const float4*>(arp + kOff);
        const uint32_t aH = sb + buf * STG_STRIDE + OFF_AH;
        #pragma unroll
        for (int g = 0; g < 4; ++g) {
            const float4 xa = xr[2 * g], xb = xr[2 * g + 1];
            const float4 ra = rp4[2 * g], rb = rp4[2 * g + 1];
            uint32_t h[4], l[4];
            h[0] = bsplit2(xa.x * ra.x, xa.y * ra.y, l[0]);
            h[1] = bsplit2(xa.z * ra.z, xa.w * ra.w, l[1]);
            h[2] = bsplit2(xb.x * rb.x, xb.y * rb.y, l[2]);
            h[3] = bsplit2(xb.z * rb.z, xb.w * rb.w, l[3]);
            STS128(aH + sA[g], h[0], h[1], h[2], h[3]);
            STS128(aH + sA[g] + OFF_AL, l[0], l[1], l[2], l[3]);
        }
    };
    auto ldB = [&](int kOff, int buf) {
        const uint32_t bH = sb + buf * STG_STRIDE + OFF_BH;
        const char* gh = (const char*)g_wh4;
        const char* gl = (const char*)g_wl4;
        #pragma unroll
        for (int it = 0; it < 4; ++it) {
            const int idx = it * 256 + tid;          // 1024 16B-vectors
            const int ol = idx >> 3;
            const int kq = idx & 7;
            const size_t gb = ((size_t)(oBase + ol) * CIN + kOff + kq * 8) * 2;
            const uint32_t off = (uint32_t)(ol * 128) +
                                 (((uint32_t)(kq * 16)) ^ ((uint32_t)(ol & 7) * 16));
            CP16(bH + off, gh + gb);
            CP16(bH + off + 16384, gl + gb);
        }
    };
    auto compute = [&](int buf) {
        const uint32_t base = sb + buf * STG_STRIDE;
        #pragma unroll
        for (int kk = 0; kk < 4; ++kk) {
            const uint32_t kbl = (uint32_t)(kk * 32 + lkh * 16);
            uint32_t Ah[2][4], Al[2][4], Bh[4][4], Bl[4][4];
            #pragma unroll
            for (int mt = 0; mt < 2; ++mt) {
                const uint32_t ad = base + OFF_AH + aBase[mt] + (kbl ^ aXm[mt]);
                LDSM4(Ah[mt], ad);
                LDSM4(Al[mt], ad + OFF_AL);
            }
            #pragma unroll
            for (int nt = 0; nt < 4; ++nt) {
                const uint32_t bd = base + OFF_BH + bBase[nt] + (kbl ^ bXm[nt]);
                LDSM4(Bh[nt], bd);
                LDSM4(Bl[nt], bd + 16384);
            }
            #pragma unroll
            for (int nt = 0; nt < 4; ++nt)
                #pragma unroll
                for (int mt = 0; mt < 2; ++mt) {
                    MMA16816(acc[mt][nt * 2],     Ah[mt], Bh[nt][0], Bh[nt][2]);
                    MMA16816(acc[mt][nt * 2 + 1], Ah[mt], Bh[nt][1], Bh[nt][3]);
                    MMA16816(acc[mt][nt * 2],     Al[mt], Bh[nt][0], Bh[nt][2]);
                    MMA16816(acc[mt][nt * 2 + 1], Al[mt], Bh[nt][1], Bh[nt][3]);
                    MMA16816(acc[mt][nt * 2],     Ah[mt], Bl[nt][0], Bl[nt][2]);
                    MMA16816(acc[mt][nt * 2 + 1], Ah[mt], Bl[nt][1], Bl[nt][3]);
                }
        }
    };

    // ---- prologue ----
    ldgA(0);
    ldB(0, 0); CP_COMMIT();
    stsA(0, 0);
    ldgA(64);
    ldB(64, 1); CP_COMMIT();
    CP_WAIT1();
    __syncthreads();

    // ---- mainloop ----
    #pragma unroll 1
    for (int kc = 0; kc < 6; ++kc) {
        const int buf = kc & 1;
        if (kc < 5) {
            stsA((kc + 1) * 64, buf ^ 1);    // A for next chunk (regs -> other buffer)
            if (kc < 4) ldgA((kc + 2) * 64); // prefetch x two chunks ahead
        }
        compute(buf);
        if (kc < 5) {
            __syncthreads();                 // all warps done reading buf's B (race fix)
            if (kc < 4) {
                ldB((kc + 2) * 64, buf); CP_COMMIT();
                CP_WAIT1();
            } else {
                CP_WAIT0();
            }
            __syncthreads();                 // cp.async data + stsA visible to all
        }
    }

    // ---- epilogue ----
    #pragma unroll
    for (int mt = 0; mt < 2; ++mt)
        #pragma unroll
        for (int rh = 0; rh < 2; ++rh) {
            const int m = mBase + wm + mt * 16 + (lane >> 2) + rh * 8;
            const int bt = m / NTOK;
            const int n = m - bt * NTOK;
            float* op = out + (size_t)bt * OUT_BT_STRIDE + n;
            const float* rr = g_r + (size_t)bt * COUT + oBase + wn;
            const float* bb = bias + oBase + wn;
            #pragma unroll
            for (int nt2 = 0; nt2 < 8; ++nt2) {
                const int c0 = nt2 * 8 + (lane & 3) * 2;
                const float v0 = acc[mt][nt2][rh * 2 + 0] + bb[c0] * rr[c0];
                const float v1 = acc[mt][nt2][rh * 2 + 1] + bb[c0 + 1] * rr[c0 + 1];
                op[(size_t)(oBase + wn + c0) * NTOK] = v0;
                op[(size_t)(oBase + wn + c0 + 1) * NTOK] = v1;
            }
        }
}

// ======================= launch =======================
extern "C" void kernel_launch(void* const* d_in, const int* in_sizes, int n_in,
                              void* d_out, int out_size) {
    const float* x = (const float*)d_in[0];
    const float* rf_w = (const float*)d_in[1];
    const float* rf_b = (const float*)d_in[2];
    const float* moe_w = (const float*)d_in[3];
    const float* moe_b = (const float*)d_in[4];
    const float* weight = (const float*)d_in[5];
    const float* bias = (const float*)d_in[6];
    float* out = (float*)d_out;

    cudaFuncSetAttribute(k_main, cudaFuncAttributeMaxDynamicSharedMemorySize, SMEM_MAIN);
    cudaFuncSetAttribute(k_routing, cudaFuncAttributeMaxDynamicSharedMemorySize, 61440);

    k_rf<<<32, 128>>>(x, rf_w, rf_b);
    k_wsplit<<<216, 256>>>(weight);
    k_routing<<<dim3(144, 8), 256, 61440>>>(x, moe_w, moe_b);
    k_main<<<dim3(9, 394), 256, SMEM_MAIN>>>(x, bias, out);
}

// round 7
// speedup vs baseline: 1.6474x; 1.0196x over previous
#include <cuda_runtime.h>
#include <cuda_bf16.h>
#include <cstdint>

#define NTOK 197
#define CIN 384
#define COUT 1152
#define TT 8
#define OUT_BT_STRIDE (COUT * NTOK)

__device__ float g_rf[32 * 4];
__device__ float g_r[256 * COUT];
__device__ uint4 g_wh4[COUT * CIN / 8];   // weight hi bf16, [o][k] row-major
__device__ uint4 g_wl4[COUT * CIN / 8];   // weight lo bf16

// ======================= helpers =======================
__device__ __forceinline__ uint32_t smem_u32(const void* p) {
    uint32_t a;
    asm("{ .reg .u64 t; cvta.to.shared.u64 t, %1; cvt.u32.u64 %0, t; }" : "=r"(a) : "l"(p));
    return a;
}
__device__ __forceinline__ uint32_t bsplit2(float a, float b, uint32_t& lo) {
    __nv_bfloat162 h = __floats2bfloat162_rn(a, b);
    float2 hf = __bfloat1622float2(h);
    __nv_bfloat162 l = __floats2bfloat162_rn(a - hf.x, b - hf.y);
    lo = *reinterpret_cast<uint32_t*>(&l);
    return *reinterpret_cast<uint32_t*>(&h);
}
#define STS128(a, v0, v1, v2, v3) \
    asm volatile("st.shared.v4.b32 [%0], {%1, %2, %3, %4};" :: "r"(a), "r"(v0), "r"(v1), "r"(v2), "r"(v3) : "memory")
#define CP16(dst, src) \
    asm volatile("cp.async.cg.shared.global [%0], [%1], 16;" :: "r"(dst), "l"(src) : "memory")
#define CP_COMMIT() asm volatile("cp.async.commit_group;" ::: "memory")
#define CP_WAIT1() asm volatile("cp.async.wait_group 1;" ::: "memory")
#define CP_WAIT0() asm volatile("cp.async.wait_group 0;" ::: "memory")
#define LDSM4(r, a)                                                                   \
    asm volatile("ldmatrix.sync.aligned.m8n8.x4.shared.b16 {%0,%1,%2,%3}, [%4];"      \
        : "=r"((r)[0]), "=r"((r)[1]), "=r"((r)[2]), "=r"((r)[3]) : "r"(a))
// NOTE: non-volatile — pure register op, lets ptxas schedule/interleave.
#define MMA16816(d, a, b0, b1)                                                        \
    asm("mma.sync.aligned.m16n8k16.row.col.f32.bf16.bf16.f32 "                        \
        "{%0,%1,%2,%3}, {%4,%5,%6,%7}, {%8,%9}, {%0,%1,%2,%3};"                       \
        : "+f"((d)[0]), "+f"((d)[1]), "+f"((d)[2]), "+f"((d)[3])                      \
        : "r"((a)[0]), "r"((a)[1]), "r"((a)[2]), "r"((a)[3]), "r"(b0), "r"(b1))

// ======================= Kernel 0: weight bf16 hi/lo split =======================
__global__ void k_wsplit(const float* __restrict__ w) {
    int i = blockIdx.x * 256 + threadIdx.x;
    const float4 v0 = reinterpret_cast<const float4*>(w)[i * 2];
    const float4 v1 = reinterpret_cast<const float4*>(w)[i * 2 + 1];
    uint32_t h[4], l[4];
    h[0] = bsplit2(v0.x, v0.y, l[0]);
    h[1] = bsplit2(v0.z, v0.w, l[1]);
    h[2] = bsplit2(v1.x, v1.y, l[2]);
    h[3] = bsplit2(v1.z, v1.w, l[3]);
    g_wh4[i] = make_uint4(h[0], h[1], h[2], h[3]);
    g_wl4[i] = make_uint4(l[0], l[1], l[2], l[3]);
}

// ======================= Kernel 1: rf =======================
__global__ void k_rf(const float* __restrict__ x, const float* __restrict__ rf_w,
                     const float* __restrict__ rf_b) {
    const int b = blockIdx.x;
    const int tid = threadIdx.x;
    float a0 = 0.f, a1 = 0.f, a2 = 0.f, a3 = 0.f;
    for (int c = tid; c < CIN; c += 128) {
        float p = 0.f;
        #pragma unroll
        for (int t = 0; t < TT; ++t)
            p += x[(size_t)(b * TT + t) * NTOK * CIN + c];
        p *= 0.125f;
        a0 += p * rf_w[0 * CIN + c];
        a1 += p * rf_w[1 * CIN + c];
        a2 += p * rf_w[2 * CIN + c];
        a3 += p * rf_w[3 * CIN + c];
    }
    __shared__ float red[4][128];
    red[0][tid] = a0; red[1][tid] = a1; red[2][tid] = a2; red[3][tid] = a3;
    __syncthreads();
    for (int s = 64; s > 0; s >>= 1) {
        if (tid < s) {
            red[0][tid] += red[0][tid + s];
            red[1][tid] += red[1][tid + s];
            red[2][tid] += red[2][tid + s];
            red[3][tid] += red[3][tid + s];
        }
        __syncthreads();
    }
    if (tid < 4) g_rf[b * 4 + tid] = red[tid][0] + rf_b[tid];
}

// ======================= Kernel 2: routing =======================
__global__ __launch_bounds__(256) void k_routing(const float* __restrict__ x,
                                                 const float* __restrict__ moe_w,
                                                 const float* __restrict__ moe_b) {
    extern __shared__ float rsm[];            // clsp[4][384][10]
    __shared__ float srf[16];
    const int tid = threadIdx.x, lane = tid & 31, wid = tid >> 5;
    const int o = blockIdx.x * 8 + wid;
    const int b0 = blockIdx.y * 4;

    if (tid < 16) srf[tid] = g_rf[(b0 + (tid >> 2)) * 4 + (tid & 3)];
    #pragma unroll 1
    for (int it = 0; it < 48; ++it) {
        int e = it * 256 + tid;
        int bi = e / 3072;
        int r2 = e - bi * 3072;
        int t = r2 / CIN;
        int c = r2 - t * CIN;
        rsm[bi * 3840 + c * 10 + t + 1] =
            x[(size_t)((b0 + bi) * TT + t) * NTOK * CIN + c];
    }
    #pragma unroll 1
    for (int it = 0; it < 12; ++it) {
        int e = it * 256 + tid;
        int bi = e / 768;
        int r2 = e - bi * 768;
        int c = r2 >> 1;
        rsm[bi * 3840 + c * 10 + (r2 & 1) * 9] = 0.f;
    }
    __syncthreads();

    float f[16];
    #pragma unroll
    for (int i = 0; i < 16; ++i) f[i] = srf[i];

    float vals[32];
    #pragma unroll
    for (int i = 0; i < 32; ++i) vals[i] = 0.f;

    #pragma unroll 1
    for (int ci = 0; ci < 12; ++ci) {
        const int c = ci * 32 + lane;
        float w[4][3];
        #pragma unroll
        for (int e = 0; e < 4; ++e) {
            const float* wp = moe_w + ((size_t)(e * COUT + o) * CIN + c) * 3;
            w[e][0] = wp[0]; w[e][1] = wp[1]; w[e][2] = wp[2];
        }
        #pragma unroll
        for (int bi = 0; bi < 4; ++bi) {
            const float f0 = f[bi * 4 + 0], f1 = f[bi * 4 + 1];
            const float f2 = f[bi * 4 + 2], f3 = f[bi * 4 + 3];
            const float wv0 = f0 * w[0][0] + f1 * w[1][0] + f2 * w[2][0] + f3 * w[3][0];
            const float wv1 = f0 * w[0][1] + f1 * w[1][1] + f2 * w[2][1] + f3 * w[3][1];
            const float wv2 = f0 * w[0][2] + f1 * w[1][2] + f2 * w[2][2] + f3 * w[3][2];
            const float* cl = rsm + bi * 3840 + c * 10;
            float cv[10];
            #pragma unroll
            for (int t = 0; t < 10; ++t) cv[t] = cl[t];
            #pragma unroll
            for (int t = 0; t < TT; ++t)
                vals[bi * 8 + t] += wv0 * cv[t] + wv1 * cv[t + 1] + wv2 * cv[t + 2];
        }
    }

    int cnt = 32;
    #pragma unroll
    for (int off = 16; off; off >>= 1) {
        cnt >>= 1;
        #pragma unroll 16
        for (int j = 0; j < cnt; ++j) {
            const float send = (lane & off) ? vals[j] : vals[j + cnt];
            const float other = __shfl_xor_sync(0xffffffffu, send, off);
            vals[j] = ((lane & off) ? vals[j + cnt] : vals[j]) + other;
        }
    }
    {
        const int bi = lane >> 3, t = lane & 7;
        float bo = 1.0f;
        #pragma unroll
        for (int e = 0; e < 4; ++e) bo += f[bi * 4 + e] * moe_b[e * COUT + o];
        g_r[(size_t)((b0 + bi) * TT + t) * COUT + o] = vals[0] + bo;
    }
}

// ======================= Kernel 3: main mma.sync GEMM =======================
// CTA 128m x 128o, K=384 in 6 chunks of 64 bf16 (SW128 rows). Split-bf16 3-pass.
// Pass-major MMA order (16 independent accs between reuses); r staged in smem.
#define STG_STRIDE 65536
#define OFF_AH 0
#define OFF_AL 16384
#define OFF_BH 32768
#define OFF_BL 49152
#define OFF_SR (2 * STG_STRIDE)
#define SMEM_MAIN (1024 + 2 * STG_STRIDE + 4096)

__global__ __launch_bounds__(256, 1) void k_main(const float* __restrict__ x,
                                                 const float* __restrict__ bias,
                                                 float* __restrict__ out) {
    extern __shared__ char dsm[];
    const uint32_t sb = (smem_u32(dsm) + 1023u) & ~1023u;
    char* dsm_al = dsm + (sb - smem_u32(dsm));
    float* sr = reinterpret_cast<float*>(dsm_al + OFF_SR);   // [2][384]
    const int tid = threadIdx.x, lane = tid & 31, wid = tid >> 5;
    const int oBase = blockIdx.x * 128;
    const int s = blockIdx.x / 3;
    const int mBase = blockIdx.y * 128;
    const int bt0 = mBase / NTOK;
    const int bt1 = (mBase + 127) / NTOK;

    // A loader mapping: 2 threads per row, 32 k each
    const int arow = tid >> 1;
    const int ahalf = tid & 1;
    const int am = mBase + arow;
    const int abt = am / NTOK;
    const float* axp = x + (size_t)am * CIN + ahalf * 32;
    const float* srow = sr + (abt != bt0 ? 384 : 0) + ahalf * 32;

    // hoisted swizzled STS offsets for A
    uint32_t sA[4];
    {
        const uint32_t xm = (uint32_t)(arow & 7) * 16;
        #pragma unroll
        for (int g = 0; g < 4; ++g)
            sA[g] = (uint32_t)arow * 128 + (((uint32_t)(ahalf * 64 + g * 16)) ^ xm);
    }

    // warp tile: 4m x 2n warps, each 32m x 64o
    const int wm = (wid & 3) * 32;
    const int wn = (wid >> 2) * 64;

    const int lrow = lane & 15, lkh = lane >> 4;
    uint32_t aBase[2], aXm[2], bBase[4], bXm[4];
    #pragma unroll
    for (int mt = 0; mt < 2; ++mt) {
        const int row = wm + mt * 16 + lrow;
        aBase[mt] = (uint32_t)row * 128;
        aXm[mt] = (uint32_t)(row & 7) * 16;
    }
    #pragma unroll
    for (int nt = 0; nt < 4; ++nt) {
        const int row = wn + nt * 16 + lrow;
        bBase[nt] = (uint32_t)row * 128;
        bXm[nt] = (uint32_t)(row & 7) * 16;
    }

    float acc[2][8][4];
    #pragma unroll
    for (int i = 0; i < 2; ++i)
        #pragma unroll
        for (int j = 0; j < 8; ++j)
            #pragma unroll
            for (int e = 0; e < 4; ++e) acc[i][j][e] = 0.f;

    float4 xr[8];

    auto ldgA = [&](int kOff) {
        const float4* xp4 = reinterpret_cast<const float4*>(axp + kOff);
        #pragma unroll
        for (int i = 0; i < 8; ++i) xr[i] = xp4[i];
    };
    auto stsA = [&](int kOff, int buf) {
        const float4* rp4 = reinterpret_cast<const float4*>(srow + kOff);  // smem (bcast)
        const uint32_t aH = sb + buf * STG_STRIDE + OFF_AH;
        #pragma unroll
        for (int g = 0; g < 4; ++g) {
            const float4 xa = xr[2 * g], xb = xr[2 * g + 1];
            const float4 ra = rp4[2 * g], rb = rp4[2 * g + 1];
            uint32_t h[4], l[4];
            h[0] = bsplit2(xa.x * ra.x, xa.y * ra.y, l[0]);
            h[1] = bsplit2(xa.z * ra.z, xa.w * ra.w, l[1]);
            h[2] = bsplit2(xb.x * rb.x, xb.y * rb.y, l[2]);
            h[3] = bsplit2(xb.z * rb.z, xb.w * rb.w, l[3]);
            STS128(aH + sA[g], h[0], h[1], h[2], h[3]);
            STS128(aH + sA[g] + OFF_AL, l[0], l[1], l[2], l[3]);
        }
    };
    auto ldB = [&](int kOff, int buf) {
        const uint32_t bH = sb + buf * STG_STRIDE + OFF_BH;
        const char* gh = (const char*)g_wh4;
        const char* gl = (const char*)g_wl4;
        #pragma unroll
        for (int it = 0; it < 4; ++it) {
            const int idx = it * 256 + tid;          // 1024 16B-vectors
            const int ol = idx >> 3;
            const int kq = idx & 7;
            const size_t gb = ((size_t)(oBase + ol) * CIN + kOff + kq * 8) * 2;
            const uint32_t off = (uint32_t)(ol * 128) +
                                 (((uint32_t)(kq * 16)) ^ ((uint32_t)(ol & 7) * 16));
            CP16(bH + off, gh + gb);
            CP16(bH + off + 16384, gl + gb);
        }
    };
    auto compute = [&](int buf) {
        const uint32_t base = sb + buf * STG_STRIDE;
        #pragma unroll
        for (int kk = 0; kk < 4; ++kk) {
            const uint32_t kbl = (uint32_t)(kk * 32 + lkh * 16);
            uint32_t Ah[2][4], Al[2][4], Bh[4][4], Bl[4][4];
            #pragma unroll
            for (int mt = 0; mt < 2; ++mt) {
                const uint32_t ad = base + OFF_AH + aBase[mt] + (kbl ^ aXm[mt]);
                LDSM4(Ah[mt], ad);
            }
            #pragma unroll
            for (int nt = 0; nt < 4; ++nt) {
                const uint32_t bd = base + OFF_BH + bBase[nt] + (kbl ^ bXm[nt]);
                LDSM4(Bh[nt], bd);
            }
            #pragma unroll
            for (int mt = 0; mt < 2; ++mt) {
                const uint32_t ad = base + OFF_AH + aBase[mt] + (kbl ^ aXm[mt]);
                LDSM4(Al[mt], ad + OFF_AL);
            }
            #pragma unroll
            for (int nt = 0; nt < 4; ++nt) {
                const uint32_t bd = base + OFF_BH + bBase[nt] + (kbl ^ bXm[nt]);
                LDSM4(Bl[nt], bd + 16384);
            }
            // pass-major: 16 independent MMAs between accumulator reuses
            #pragma unroll
            for (int nt = 0; nt < 4; ++nt)
                #pragma unroll
                for (int mt = 0; mt < 2; ++mt) {
                    MMA16816(acc[mt][nt * 2],     Ah[mt], Bh[nt][0], Bh[nt][2]);
                    MMA16816(acc[mt][nt * 2 + 1], Ah[mt], Bh[nt][1], Bh[nt][3]);
                }
            #pragma unroll
            for (int nt = 0; nt < 4; ++nt)
                #pragma unroll
                for (int mt = 0; mt < 2; ++mt) {
                    MMA16816(acc[mt][nt * 2],     Al[mt], Bh[nt][0], Bh[nt][2]);
                    MMA16816(acc[mt][nt * 2 + 1], Al[mt], Bh[nt][1], Bh[nt][3]);
                }
            #pragma unroll
            for (int nt = 0; nt < 4; ++nt)
                #pragma unroll
                for (int mt = 0; mt < 2; ++mt) {
                    MMA16816(acc[mt][nt * 2],     Ah[mt], Bl[nt][0], Bl[nt][2]);
                    MMA16816(acc[mt][nt * 2 + 1], Ah[mt], Bl[nt][1], Bl[nt][3]);
                }
        }
    };

    // ---- prologue ----
    #pragma unroll
    for (int i = 0; i < 3; ++i) {
        const int e = i * 256 + tid;          // 768 = 2 x 384
        const int sel = e >> 9 ? 1 : (e >= 384);
        const int c = e - (e >= 384 ? 384 : 0);
        sr[e] = g_r[(size_t)(e >= 384 ? bt1 : bt0) * COUT + s * CIN + c];
        (void)sel;
    }
    ldB(0, 0); CP_COMMIT();
    ldgA(0);
    __syncthreads();                          // sr visible before stsA reads it
    stsA(0, 0);
    ldgA(64);
    ldB(64, 1); CP_COMMIT();
    CP_WAIT1();
    __syncthreads();

    // ---- mainloop ----
    #pragma unroll 1
    for (int kc = 0; kc < 6; ++kc) {
        const int buf = kc & 1;
        if (kc < 5) {
            stsA((kc + 1) * 64, buf ^ 1);     // pure ALU+STS now (r from smem)
            if (kc < 4) ldgA((kc + 2) * 64);  // LDG latency hidden under compute
        }
        compute(buf);
        if (kc < 5) {
            __syncthreads();                  // all warps done reading buf's B
            if (kc < 4) {
                ldB((kc + 2) * 64, buf); CP_COMMIT();
                CP_WAIT1();
            } else {
                CP_WAIT0();
            }
            __syncthreads();                  // cp.async data + stsA visible
        }
    }

    // ---- epilogue ----
    #pragma unroll
    for (int mt = 0; mt < 2; ++mt)
        #pragma unroll
        for (int rh = 0; rh < 2; ++rh) {
            const int m = mBase + wm + mt * 16 + (lane >> 2) + rh * 8;
            const int bt = m / NTOK;
            const int n = m - bt * NTOK;
            float* op = out + (size_t)bt * OUT_BT_STRIDE + n;
            const float* rr = g_r + (size_t)bt * COUT + oBase + wn;
            const float* bb = bias + oBase + wn;
            #pragma unroll
            for (int nt2 = 0; nt2 < 8; ++nt2) {
                const int c0 = nt2 * 8 + (lane & 3) * 2;
                const float v0 = acc[mt][nt2][rh * 2 + 0] + bb[c0] * rr[c0];
                const float v1 = acc[mt][nt2][rh * 2 + 1] + bb[c0 + 1] * rr[c0 + 1];
                op[(size_t)(oBase + wn + c0) * NTOK] = v0;
                op[(size_t)(oBase + wn + c0 + 1) * NTOK] = v1;
            }
        }
}

// ======================= launch =======================
extern "C" void kernel_launch(void* const* d_in, const int* in_sizes, int n_in,
                              void* d_out, int out_size) {
    const float* x = (const float*)d_in[0];
    const float* rf_w = (const float*)d_in[1];
    const float* rf_b = (const float*)d_in[2];
    const float* moe_w = (const float*)d_in[3];
    const float* moe_b = (const float*)d_in[4];
    const float* weight = (const float*)d_in[5];
    const float* bias = (const float*)d_in[6];
    float* out = (float*)d_out;

    cudaFuncSetAttribute(k_main, cudaFuncAttributeMaxDynamicSharedMemorySize, SMEM_MAIN);
    cudaFuncSetAttribute(k_routing, cudaFuncAttributeMaxDynamicSharedMemorySize, 61440);

    k_rf<<<32, 128>>>(x, rf_w, rf_b);
    k_wsplit<<<216, 256>>>(weight);
    k_routing<<<dim3(144, 8), 256, 61440>>>(x, moe_w, moe_b);
    k_main<<<dim3(9, 394), 256, SMEM_MAIN>>>(x, bias, out);
}

// round 8
// speedup vs baseline: 1.6488x; 1.0008x over previous
#include <cuda_runtime.h>
#include <cuda_bf16.h>
#include <cstdint>

#define NTOK 197
#define CIN 384
#define COUT 1152
#define TT 8
#define OUT_BT_STRIDE (COUT * NTOK)

__device__ float g_rf[32 * 4];
__device__ float g_r[256 * COUT];
__device__ uint4 g_wh4[COUT * CIN / 8];   // weight hi bf16, [o][k] row-major
__device__ uint4 g_wl4[COUT * CIN / 8];   // weight lo bf16

// ======================= helpers =======================
__device__ __forceinline__ uint32_t smem_u32(const void* p) {
    uint32_t a;
    asm("{ .reg .u64 t; cvta.to.shared.u64 t, %1; cvt.u32.u64 %0, t; }" : "=r"(a) : "l"(p));
    return a;
}
__device__ __forceinline__ uint32_t bsplit2(float a, float b, uint32_t& lo) {
    __nv_bfloat162 h = __floats2bfloat162_rn(a, b);
    float2 hf = __bfloat1622float2(h);
    __nv_bfloat162 l = __floats2bfloat162_rn(a - hf.x, b - hf.y);
    lo = *reinterpret_cast<uint32_t*>(&l);
    return *reinterpret_cast<uint32_t*>(&h);
}
#define STS128(a, v0, v1, v2, v3) \
    asm volatile("st.shared.v4.b32 [%0], {%1, %2, %3, %4};" :: "r"(a), "r"(v0), "r"(v1), "r"(v2), "r"(v3) : "memory")
#define CP16(dst, src) \
    asm volatile("cp.async.cg.shared.global [%0], [%1], 16;" :: "r"(dst), "l"(src) : "memory")
#define CP_COMMIT() asm volatile("cp.async.commit_group;" ::: "memory")
#define CP_WAIT1() asm volatile("cp.async.wait_group 1;" ::: "memory")
#define CP_WAIT0() asm volatile("cp.async.wait_group 0;" ::: "memory")
#define LDSM4(r, a)                                                                   \
    asm volatile("ldmatrix.sync.aligned.m8n8.x4.shared.b16 {%0,%1,%2,%3}, [%4];"      \
        : "=r"((r)[0]), "=r"((r)[1]), "=r"((r)[2]), "=r"((r)[3]) : "r"(a))
// non-volatile: pure register op, ptxas may interleave freely
#define MMA16816(d, a, b0, b1)                                                        \
    asm("mma.sync.aligned.m16n8k16.row.col.f32.bf16.bf16.f32 "                        \
        "{%0,%1,%2,%3}, {%4,%5,%6,%7}, {%8,%9}, {%0,%1,%2,%3};"                       \
        : "+f"((d)[0]), "+f"((d)[1]), "+f"((d)[2]), "+f"((d)[3])                      \
        : "r"((a)[0]), "r"((a)[1]), "r"((a)[2]), "r"((a)[3]), "r"(b0), "r"(b1))

// ======================= Kernel 0: weight bf16 hi/lo split =======================
__global__ void k_wsplit(const float* __restrict__ w) {
    int i = blockIdx.x * 256 + threadIdx.x;
    const float4 v0 = reinterpret_cast<const float4*>(w)[i * 2];
    const float4 v1 = reinterpret_cast<const float4*>(w)[i * 2 + 1];
    uint32_t h[4], l[4];
    h[0] = bsplit2(v0.x, v0.y, l[0]);
    h[1] = bsplit2(v0.z, v0.w, l[1]);
    h[2] = bsplit2(v1.x, v1.y, l[2]);
    h[3] = bsplit2(v1.z, v1.w, l[3]);
    g_wh4[i] = make_uint4(h[0], h[1], h[2], h[3]);
    g_wl4[i] = make_uint4(l[0], l[1], l[2], l[3]);
}

// ======================= Kernel 1: rf =======================
__global__ void k_rf(const float* __restrict__ x, const float* __restrict__ rf_w,
                     const float* __restrict__ rf_b) {
    const int b = blockIdx.x;
    const int tid = threadIdx.x;
    float a0 = 0.f, a1 = 0.f, a2 = 0.f, a3 = 0.f;
    for (int c = tid; c < CIN; c += 128) {
        float p = 0.f;
        #pragma unroll
        for (int t = 0; t < TT; ++t)
            p += x[(size_t)(b * TT + t) * NTOK * CIN + c];
        p *= 0.125f;
        a0 += p * rf_w[0 * CIN + c];
        a1 += p * rf_w[1 * CIN + c];
        a2 += p * rf_w[2 * CIN + c];
        a3 += p * rf_w[3 * CIN + c];
    }
    __shared__ float red[4][128];
    red[0][tid] = a0; red[1][tid] = a1; red[2][tid] = a2; red[3][tid] = a3;
    __syncthreads();
    for (int s = 64; s > 0; s >>= 1) {
        if (tid < s) {
            red[0][tid] += red[0][tid + s];
            red[1][tid] += red[1][tid + s];
            red[2][tid] += red[2][tid + s];
            red[3][tid] += red[3][tid + s];
        }
        __syncthreads();
    }
    if (tid < 4) g_rf[b * 4 + tid] = red[tid][0] + rf_b[tid];
}

// ======================= Kernel 2: routing =======================
__global__ __launch_bounds__(256) void k_routing(const float* __restrict__ x,
                                                 const float* __restrict__ moe_w,
                                                 const float* __restrict__ moe_b) {
    extern __shared__ float rsm[];            // clsp[4][384][10]
    __shared__ float srf[16];
    const int tid = threadIdx.x, lane = tid & 31, wid = tid >> 5;
    const int o = blockIdx.x * 8 + wid;
    const int b0 = blockIdx.y * 4;

    if (tid < 16) srf[tid] = g_rf[(b0 + (tid >> 2)) * 4 + (tid & 3)];
    #pragma unroll 1
    for (int it = 0; it < 48; ++it) {
        int e = it * 256 + tid;
        int bi = e / 3072;
        int r2 = e - bi * 3072;
        int t = r2 / CIN;
        int c = r2 - t * CIN;
        rsm[bi * 3840 + c * 10 + t + 1] =
            x[(size_t)((b0 + bi) * TT + t) * NTOK * CIN + c];
    }
    #pragma unroll 1
    for (int it = 0; it < 12; ++it) {
        int e = it * 256 + tid;
        int bi = e / 768;
        int r2 = e - bi * 768;
        int c = r2 >> 1;
        rsm[bi * 3840 + c * 10 + (r2 & 1) * 9] = 0.f;
    }
    __syncthreads();

    float f[16];
    #pragma unroll
    for (int i = 0; i < 16; ++i) f[i] = srf[i];

    float vals[32];
    #pragma unroll
    for (int i = 0; i < 32; ++i) vals[i] = 0.f;

    #pragma unroll 1
    for (int ci = 0; ci < 12; ++ci) {
        const int c = ci * 32 + lane;
        float w[4][3];
        #pragma unroll
        for (int e = 0; e < 4; ++e) {
            const float* wp = moe_w + ((size_t)(e * COUT + o) * CIN + c) * 3;
            w[e][0] = wp[0]; w[e][1] = wp[1]; w[e][2] = wp[2];
        }
        #pragma unroll
        for (int bi = 0; bi < 4; ++bi) {
            const float f0 = f[bi * 4 + 0], f1 = f[bi * 4 + 1];
            const float f2 = f[bi * 4 + 2], f3 = f[bi * 4 + 3];
            const float wv0 = f0 * w[0][0] + f1 * w[1][0] + f2 * w[2][0] + f3 * w[3][0];
            const float wv1 = f0 * w[0][1] + f1 * w[1][1] + f2 * w[2][1] + f3 * w[3][1];
            const float wv2 = f0 * w[0][2] + f1 * w[1][2] + f2 * w[2][2] + f3 * w[3][2];
            const float* cl = rsm + bi * 3840 + c * 10;
            float cv[10];
            #pragma unroll
            for (int t = 0; t < 10; ++t) cv[t] = cl[t];
            #pragma unroll
            for (int t = 0; t < TT; ++t)
                vals[bi * 8 + t] += wv0 * cv[t] + wv1 * cv[t + 1] + wv2 * cv[t + 2];
        }
    }

    int cnt = 32;
    #pragma unroll
    for (int off = 16; off; off >>= 1) {
        cnt >>= 1;
        #pragma unroll 16
        for (int j = 0; j < cnt; ++j) {
            const float send = (lane & off) ? vals[j] : vals[j + cnt];
            const float other = __shfl_xor_sync(0xffffffffu, send, off);
            vals[j] = ((lane & off) ? vals[j + cnt] : vals[j]) + other;
        }
    }
    {
        const int bi = lane >> 3, t = lane & 7;
        float bo = 1.0f;
        #pragma unroll
        for (int e = 0; e < 4; ++e) bo += f[bi * 4 + e] * moe_b[e * COUT + o];
        g_r[(size_t)((b0 + bi) * TT + t) * COUT + o] = vals[0] + bo;
    }
}

// ======================= Kernel 3: main mma.sync GEMM =======================
// CTA 128m x 128o, K=384 in 6 chunks of 64 bf16 (SW128 rows). Split-bf16 3-pass.
// kk-level software pipeline: fragments double-buffered; ldfrag(kk+1) issued
// before the 48 MMAs of kk, so LDSM latency + L1 queueing hides under tensor work.
#define STG_STRIDE 65536
#define OFF_AH 0
#define OFF_AL 16384
#define OFF_BH 32768
#define OFF_BL 49152
#define OFF_SR (2 * STG_STRIDE)
#define SMEM_MAIN (1024 + 2 * STG_STRIDE + 4096)

__global__ __launch_bounds__(256, 1) void k_main(const float* __restrict__ x,
                                                 const float* __restrict__ bias,
                                                 float* __restrict__ out) {
    extern __shared__ char dsm[];
    const uint32_t sb = (smem_u32(dsm) + 1023u) & ~1023u;
    char* dsm_al = dsm + (sb - smem_u32(dsm));
    float* sr = reinterpret_cast<float*>(dsm_al + OFF_SR);   // [2][384]
    const int tid = threadIdx.x, lane = tid & 31, wid = tid >> 5;
    const int oBase = blockIdx.x * 128;
    const int s = blockIdx.x / 3;
    const int mBase = blockIdx.y * 128;
    const int bt0 = mBase / NTOK;
    const int bt1 = (mBase + 127) / NTOK;

    // A loader mapping: 2 threads per row, 32 k each
    const int arow = tid >> 1;
    const int ahalf = tid & 1;
    const int am = mBase + arow;
    const int abt = am / NTOK;
    const float* axp = x + (size_t)am * CIN + ahalf * 32;
    const float* srow = sr + (abt != bt0 ? 384 : 0) + ahalf * 32;

    // hoisted swizzled STS offsets for A
    uint32_t sA[4];
    {
        const uint32_t xm = (uint32_t)(arow & 7) * 16;
        #pragma unroll
        for (int g = 0; g < 4; ++g)
            sA[g] = (uint32_t)arow * 128 + (((uint32_t)(ahalf * 64 + g * 16)) ^ xm);
    }

    // warp tile: 4m x 2n warps, each 32m x 64o
    const int wm = (wid & 3) * 32;
    const int wn = (wid >> 2) * 64;

    const int lrow = lane & 15, lkh = lane >> 4;
    uint32_t aBase[2], aXm[2], bBase[4], bXm[4];
    #pragma unroll
    for (int mt = 0; mt < 2; ++mt) {
        const int row = wm + mt * 16 + lrow;
        aBase[mt] = (uint32_t)row * 128;
        aXm[mt] = (uint32_t)(row & 7) * 16;
    }
    #pragma unroll
    for (int nt = 0; nt < 4; ++nt) {
        const int row = wn + nt * 16 + lrow;
        bBase[nt] = (uint32_t)row * 128;
        bXm[nt] = (uint32_t)(row & 7) * 16;
    }

    float acc[2][8][4];
    #pragma unroll
    for (int i = 0; i < 2; ++i)
        #pragma unroll
        for (int j = 0; j < 8; ++j)
            #pragma unroll
            for (int e = 0; e < 4; ++e) acc[i][j][e] = 0.f;

    float4 xr[8];

    auto ldgA = [&](int kOff) {
        const float4* xp4 = reinterpret_cast<const float4*>(axp + kOff);
        #pragma unroll
        for (int i = 0; i < 8; ++i) xr[i] = xp4[i];
    };
    auto stsA = [&](int kOff, int buf) {
        const float4* rp4 = reinterpret_cast<const float4*>(srow + kOff);  // smem (bcast)
        const uint32_t aH = sb + buf * STG_STRIDE + OFF_AH;
        #pragma unroll
        for (int g = 0; g < 4; ++g) {
            const float4 xa = xr[2 * g], xb = xr[2 * g + 1];
            const float4 ra = rp4[2 * g], rb = rp4[2 * g + 1];
            uint32_t h[4], l[4];
            h[0] = bsplit2(xa.x * ra.x, xa.y * ra.y, l[0]);
            h[1] = bsplit2(xa.z * ra.z, xa.w * ra.w, l[1]);
            h[2] = bsplit2(xb.x * rb.x, xb.y * rb.y, l[2]);
            h[3] = bsplit2(xb.z * rb.z, xb.w * rb.w, l[3]);
            STS128(aH + sA[g], h[0], h[1], h[2], h[3]);
            STS128(aH + sA[g] + OFF_AL, l[0], l[1], l[2], l[3]);
        }
    };
    auto ldB = [&](int kOff, int buf) {
        const uint32_t bH = sb + buf * STG_STRIDE + OFF_BH;
        const char* gh = (const char*)g_wh4;
        const char* gl = (const char*)g_wl4;
        #pragma unroll
        for (int it = 0; it < 4; ++it) {
            const int idx = it * 256 + tid;          // 1024 16B-vectors
            const int ol = idx >> 3;
            const int kq = idx & 7;
            const size_t gb = ((size_t)(oBase + ol) * CIN + kOff + kq * 8) * 2;
            const uint32_t off = (uint32_t)(ol * 128) +
                                 (((uint32_t)(kq * 16)) ^ ((uint32_t)(ol & 7) * 16));
            CP16(bH + off, gh + gb);
            CP16(bH + off + 16384, gl + gb);
        }
    };

    // fragment double buffers (pipelined over kk)
    uint32_t Ah[2][2][4], Al[2][2][4], Bh[2][4][4], Bl[2][4][4];

    auto ldfrag = [&](uint32_t base, int kk, int pb) {
        const uint32_t kbl = (uint32_t)(kk * 32 + lkh * 16);
        #pragma unroll
        for (int mt = 0; mt < 2; ++mt) {
            const uint32_t ad = base + OFF_AH + aBase[mt] + (kbl ^ aXm[mt]);
            LDSM4(Ah[pb][mt], ad);
            LDSM4(Al[pb][mt], ad + OFF_AL);
        }
        #pragma unroll
        for (int nt = 0; nt < 4; ++nt) {
            const uint32_t bd = base + OFF_BH + bBase[nt] + (kbl ^ bXm[nt]);
            LDSM4(Bh[pb][nt], bd);
            LDSM4(Bl[pb][nt], bd + 16384);
        }
    };
    auto mmas = [&](int pb) {
        #pragma unroll
        for (int nt = 0; nt < 4; ++nt)
            #pragma unroll
            for (int mt = 0; mt < 2; ++mt) {
                MMA16816(acc[mt][nt * 2],     Ah[pb][mt], Bh[pb][nt][0], Bh[pb][nt][2]);
                MMA16816(acc[mt][nt * 2 + 1], Ah[pb][mt], Bh[pb][nt][1], Bh[pb][nt][3]);
            }
        #pragma unroll
        for (int nt = 0; nt < 4; ++nt)
            #pragma unroll
            for (int mt = 0; mt < 2; ++mt) {
                MMA16816(acc[mt][nt * 2],     Al[pb][mt], Bh[pb][nt][0], Bh[pb][nt][2]);
                MMA16816(acc[mt][nt * 2 + 1], Al[pb][mt], Bh[pb][nt][1], Bh[pb][nt][3]);
            }
        #pragma unroll
        for (int nt = 0; nt < 4; ++nt)
            #pragma unroll
            for (int mt = 0; mt < 2; ++mt) {
                MMA16816(acc[mt][nt * 2],     Ah[pb][mt], Bl[pb][nt][0], Bl[pb][nt][2]);
                MMA16816(acc[mt][nt * 2 + 1], Ah[pb][mt], Bl[pb][nt][1], Bl[pb][nt][3]);
            }
    };
    auto compute = [&](int buf) {
        const uint32_t base = sb + buf * STG_STRIDE;
        ldfrag(base, 0, 0);
        #pragma unroll
        for (int kk = 0; kk < 4; ++kk) {
            const int pb = kk & 1;
            if (kk < 3) ldfrag(base, kk + 1, pb ^ 1);   // prefetch next kk's frags
            mmas(pb);
        }
    };

    // ---- prologue ----
    #pragma unroll
    for (int i = 0; i < 3; ++i) {
        const int e = i * 256 + tid;          // 768 = 2 x 384
        const int c = e - (e >= 384 ? 384 : 0);
        sr[e] = g_r[(size_t)(e >= 384 ? bt1 : bt0) * COUT + s * CIN + c];
    }
    ldB(0, 0); CP_COMMIT();
    ldgA(0);
    __syncthreads();                          // sr visible before stsA reads it
    stsA(0, 0);
    ldgA(64);
    ldB(64, 1); CP_COMMIT();
    CP_WAIT1();
    __syncthreads();

    // ---- mainloop ----
    #pragma unroll 1
    for (int kc = 0; kc < 6; ++kc) {
        const int buf = kc & 1;
        if (kc < 5) {
            stsA((kc + 1) * 64, buf ^ 1);     // pure ALU+STS (r from smem)
            if (kc < 4) ldgA((kc + 2) * 64);  // LDG latency hidden under compute
        }
        compute(buf);
        if (kc < 5) {
            __syncthreads();                  // all warps done reading buf's B
            if (kc < 4) {
                ldB((kc + 2) * 64, buf); CP_COMMIT();
                CP_WAIT1();
            } else {
                CP_WAIT0();
            }
            __syncthreads();                  // cp.async data + stsA visible
        }
    }

    // ---- epilogue ----
    #pragma unroll
    for (int mt = 0; mt < 2; ++mt)
        #pragma unroll
        for (int rh = 0; rh < 2; ++rh) {
            const int m = mBase + wm + mt * 16 + (lane >> 2) + rh * 8;
            const int bt = m / NTOK;
            const int n = m - bt * NTOK;
            float* op = out + (size_t)bt * OUT_BT_STRIDE + n;
            const float* rr = g_r + (size_t)bt * COUT + oBase + wn;
            const float* bb = bias + oBase + wn;
            #pragma unroll
            for (int nt2 = 0; nt2 < 8; ++nt2) {
                const int c0 = nt2 * 8 + (lane & 3) * 2;
                const float v0 = acc[mt][nt2][rh * 2 + 0] + bb[c0] * rr[c0];
                const float v1 = acc[mt][nt2][rh * 2 + 1] + bb[c0 + 1] * rr[c0 + 1];
                op[(size_t)(oBase + wn + c0) * NTOK] = v0;
                op[(size_t)(oBase + wn + c0 + 1) * NTOK] = v1;
            }
        }
}

// ======================= launch =======================
extern "C" void kernel_launch(void* const* d_in, const int* in_sizes, int n_in,
                              void* d_out, int out_size) {
    const float* x = (const float*)d_in[0];
    const float* rf_w = (const float*)d_in[1];
    const float* rf_b = (const float*)d_in[2];
    const float* moe_w = (const float*)d_in[3];
    const float* moe_b = (const float*)d_in[4];
    const float* weight = (const float*)d_in[5];
    const float* bias = (const float*)d_in[6];
    float* out = (float*)d_out;

    cudaFuncSetAttribute(k_main, cudaFuncAttributeMaxDynamicSharedMemorySize, SMEM_MAIN);
    cudaFuncSetAttribute(k_routing, cudaFuncAttributeMaxDynamicSharedMemorySize, 61440);

    k_rf<<<32, 128>>>(x, rf_w, rf_b);
    k_wsplit<<<216, 256>>>(weight);
    k_routing<<<dim3(144, 8), 256, 61440>>>(x, moe_w, moe_b);
    k_main<<<dim3(9, 394), 256, SMEM_MAIN>>>(x, bias, out);
}

// round 9
// speedup vs baseline: 1.8171x; 1.1021x over previous
#include <cuda_runtime.h>
#include <cuda_bf16.h>
#include <cstdint>

#define NTOK 197
#define CIN 384
#define COUT 1152
#define TT 8
#define OUT_BT_STRIDE (COUT * NTOK)

__device__ float g_rf[32 * 4];
__device__ float g_r[256 * COUT];
__device__ uint4 g_wh4[COUT * CIN / 8];   // weight hi bf16, [o][k] row-major
__device__ uint4 g_wl4[COUT * CIN / 8];   // weight lo bf16

// ======================= helpers =======================
__device__ __forceinline__ uint32_t smem_u32(const void* p) {
    uint32_t a;
    asm("{ .reg .u64 t; cvta.to.shared.u64 t, %1; cvt.u32.u64 %0, t; }" : "=r"(a) : "l"(p));
    return a;
}
__device__ __forceinline__ uint32_t bsplit2(float a, float b, uint32_t& lo) {
    __nv_bfloat162 h = __floats2bfloat162_rn(a, b);
    float2 hf = __bfloat1622float2(h);
    __nv_bfloat162 l = __floats2bfloat162_rn(a - hf.x, b - hf.y);
    lo = *reinterpret_cast<uint32_t*>(&l);
    return *reinterpret_cast<uint32_t*>(&h);
}
#define STS128(a, v0, v1, v2, v3) \
    asm volatile("st.shared.v4.b32 [%0], {%1, %2, %3, %4};" :: "r"(a), "r"(v0), "r"(v1), "r"(v2), "r"(v3) : "memory")
#define CP16(dst, src) \
    asm volatile("cp.async.cg.shared.global [%0], [%1], 16;" :: "r"(dst), "l"(src) : "memory")
#define CP_COMMIT() asm volatile("cp.async.commit_group;" ::: "memory")
#define CP_WAIT1() asm volatile("cp.async.wait_group 1;" ::: "memory")
#define CP_WAIT0() asm volatile("cp.async.wait_group 0;" ::: "memory")
#define LDSM4(r, a)                                                                   \
    asm volatile("ldmatrix.sync.aligned.m8n8.x4.shared.b16 {%0,%1,%2,%3}, [%4];"      \
        : "=r"((r)[0]), "=r"((r)[1]), "=r"((r)[2]), "=r"((r)[3]) : "r"(a))
#define MMA16816(d, a, b0, b1)                                                        \
    asm("mma.sync.aligned.m16n8k16.row.col.f32.bf16.bf16.f32 "                        \
        "{%0,%1,%2,%3}, {%4,%5,%6,%7}, {%8,%9}, {%0,%1,%2,%3};"                       \
        : "+f"((d)[0]), "+f"((d)[1]), "+f"((d)[2]), "+f"((d)[3])                      \
        : "r"((a)[0]), "r"((a)[1]), "r"((a)[2]), "r"((a)[3]), "r"(b0), "r"(b1))

// ======================= Kernel 0: weight bf16 hi/lo split =======================
__global__ void k_wsplit(const float* __restrict__ w) {
    int i = blockIdx.x * 256 + threadIdx.x;
    const float4 v0 = reinterpret_cast<const float4*>(w)[i * 2];
    const float4 v1 = reinterpret_cast<const float4*>(w)[i * 2 + 1];
    uint32_t h[4], l[4];
    h[0] = bsplit2(v0.x, v0.y, l[0]);
    h[1] = bsplit2(v0.z, v0.w, l[1]);
    h[2] = bsplit2(v1.x, v1.y, l[2]);
    h[3] = bsplit2(v1.z, v1.w, l[3]);
    g_wh4[i] = make_uint4(h[0], h[1], h[2], h[3]);
    g_wl4[i] = make_uint4(l[0], l[1], l[2], l[3]);
}

// ======================= Kernel 1: rf =======================
__global__ void k_rf(const float* __restrict__ x, const float* __restrict__ rf_w,
                     const float* __restrict__ rf_b) {
    const int b = blockIdx.x;
    const int tid = threadIdx.x;
    float a0 = 0.f, a1 = 0.f, a2 = 0.f, a3 = 0.f;
    for (int c = tid; c < CIN; c += 128) {
        float p = 0.f;
        #pragma unroll
        for (int t = 0; t < TT; ++t)
            p += x[(size_t)(b * TT + t) * NTOK * CIN + c];
        p *= 0.125f;
        a0 += p * rf_w[0 * CIN + c];
        a1 += p * rf_w[1 * CIN + c];
        a2 += p * rf_w[2 * CIN + c];
        a3 += p * rf_w[3 * CIN + c];
    }
    __shared__ float red[4][128];
    red[0][tid] = a0; red[1][tid] = a1; red[2][tid] = a2; red[3][tid] = a3;
    __syncthreads();
    for (int s = 64; s > 0; s >>= 1) {
        if (tid < s) {
            red[0][tid] += red[0][tid + s];
            red[1][tid] += red[1][tid + s];
            red[2][tid] += red[2][tid + s];
            red[3][tid] += red[3][tid + s];
        }
        __syncthreads();
    }
    if (tid < 4) g_rf[b * 4 + tid] = red[tid][0] + rf_b[tid];
}

// ======================= Kernel 2: routing =======================
__global__ __launch_bounds__(256) void k_routing(const float* __restrict__ x,
                                                 const float* __restrict__ moe_w,
                                                 const float* __restrict__ moe_b) {
    extern __shared__ float rsm[];            // clsp[4][384][10]
    __shared__ float srf[16];
    const int tid = threadIdx.x, lane = tid & 31, wid = tid >> 5;
    const int o = blockIdx.x * 8 + wid;
    const int b0 = blockIdx.y * 4;

    if (tid < 16) srf[tid] = g_rf[(b0 + (tid >> 2)) * 4 + (tid & 3)];
    #pragma unroll 1
    for (int it = 0; it < 48; ++it) {
        int e = it * 256 + tid;
        int bi = e / 3072;
        int r2 = e - bi * 3072;
        int t = r2 / CIN;
        int c = r2 - t * CIN;
        rsm[bi * 3840 + c * 10 + t + 1] =
            x[(size_t)((b0 + bi) * TT + t) * NTOK * CIN + c];
    }
    #pragma unroll 1
    for (int it = 0; it < 12; ++it) {
        int e = it * 256 + tid;
        int bi = e / 768;
        int r2 = e - bi * 768;
        int c = r2 >> 1;
        rsm[bi * 3840 + c * 10 + (r2 & 1) * 9] = 0.f;
    }
    __syncthreads();

    float f[16];
    #pragma unroll
    for (int i = 0; i < 16; ++i) f[i] = srf[i];

    float vals[32];
    #pragma unroll
    for (int i = 0; i < 32; ++i) vals[i] = 0.f;

    #pragma unroll 1
    for (int ci = 0; ci < 12; ++ci) {
        const int c = ci * 32 + lane;
        float w[4][3];
        #pragma unroll
        for (int e = 0; e < 4; ++e) {
            const float* wp = moe_w + ((size_t)(e * COUT + o) * CIN + c) * 3;
            w[e][0] = wp[0]; w[e][1] = wp[1]; w[e][2] = wp[2];
        }
        #pragma unroll
        for (int bi = 0; bi < 4; ++bi) {
            const float f0 = f[bi * 4 + 0], f1 = f[bi * 4 + 1];
            const float f2 = f[bi * 4 + 2], f3 = f[bi * 4 + 3];
            const float wv0 = f0 * w[0][0] + f1 * w[1][0] + f2 * w[2][0] + f3 * w[3][0];
            const float wv1 = f0 * w[0][1] + f1 * w[1][1] + f2 * w[2][1] + f3 * w[3][1];
            const float wv2 = f0 * w[0][2] + f1 * w[1][2] + f2 * w[2][2] + f3 * w[3][2];
            const float* cl = rsm + bi * 3840 + c * 10;
            float cv[10];
            #pragma unroll
            for (int t = 0; t < 10; ++t) cv[t] = cl[t];
            #pragma unroll
            for (int t = 0; t < TT; ++t)
                vals[bi * 8 + t] += wv0 * cv[t] + wv1 * cv[t + 1] + wv2 * cv[t + 2];
        }
    }

    int cnt = 32;
    #pragma unroll
    for (int off = 16; off; off >>= 1) {
        cnt >>= 1;
        #pragma unroll 16
        for (int j = 0; j < cnt; ++j) {
            const float send = (lane & off) ? vals[j] : vals[j + cnt];
            const float other = __shfl_xor_sync(0xffffffffu, send, off);
            vals[j] = ((lane & off) ? vals[j + cnt] : vals[j]) + other;
        }
    }
    {
        const int bi = lane >> 3, t = lane & 7;
        float bo = 1.0f;
        #pragma unroll
        for (int e = 0; e < 4; ++e) bo += f[bi * 4 + e] * moe_b[e * COUT + o];
        g_r[(size_t)((b0 + bi) * TT + t) * COUT + o] = vals[0] + bo;
    }
}

// ======================= Kernel 3: main mma.sync GEMM =======================
// CTA 128m x 128o, K=384 in 6 chunks of 64 bf16. Split-bf16 3-pass.
// 512 threads / 16 warps (4m x 4n, warp tile 32m x 32o) -> 4 warps per SMSP.
#define STG_STRIDE 65536
#define OFF_AH 0
#define OFF_AL 16384
#define OFF_BH 32768
#define OFF_BL 49152
#define OFF_SR (2 * STG_STRIDE)
#define SMEM_MAIN (1024 + 2 * STG_STRIDE + 4096)

__global__ __launch_bounds__(512, 1) void k_main(const float* __restrict__ x,
                                                 const float* __restrict__ bias,
                                                 float* __restrict__ out) {
    extern __shared__ char dsm[];
    const uint32_t sb = (smem_u32(dsm) + 1023u) & ~1023u;
    char* dsm_al = dsm + (sb - smem_u32(dsm));
    float* sr = reinterpret_cast<float*>(dsm_al + OFF_SR);   // [2][384]
    const int tid = threadIdx.x, lane = tid & 31, wid = tid >> 5;
    const int oBase = blockIdx.x * 128;
    const int s = blockIdx.x / 3;
    const int mBase = blockIdx.y * 128;
    const int bt0 = mBase / NTOK;
    const int bt1 = (mBase + 127) / NTOK;

    // A loader mapping: 4 threads per row, 16 k each
    const int arow = tid >> 2;
    const int aq = tid & 3;
    const int am = mBase + arow;
    const int abt = am / NTOK;
    const float* axp = x + (size_t)am * CIN + aq * 16;
    const float* srow = sr + (abt != bt0 ? 384 : 0) + aq * 16;

    // hoisted swizzled STS offsets for A (kb = aq*32 + g*16 < 128, no carry)
    uint32_t sA[2];
    {
        const uint32_t xm = (uint32_t)(arow & 7) * 16;
        #pragma unroll
        for (int g = 0; g < 2; ++g)
            sA[g] = (uint32_t)arow * 128 + (((uint32_t)(aq * 32 + g * 16)) ^ xm);
    }

    // warp tile: 4m x 4n warps, each 32m x 32o
    const int wm = (wid & 3) * 32;
    const int wn = (wid >> 2) * 32;

    const int lrow = lane & 15, lkh = lane >> 4;
    uint32_t aBase[2], aXm[2], bBase[2], bXm[2];
    #pragma unroll
    for (int mt = 0; mt < 2; ++mt) {
        const int row = wm + mt * 16 + lrow;
        aBase[mt] = (uint32_t)row * 128;
        aXm[mt] = (uint32_t)(row & 7) * 16;
    }
    #pragma unroll
    for (int nt = 0; nt < 2; ++nt) {
        const int row = wn + nt * 16 + lrow;
        bBase[nt] = (uint32_t)row * 128;
        bXm[nt] = (uint32_t)(row & 7) * 16;
    }

    float acc[2][4][4];
    #pragma unroll
    for (int i = 0; i < 2; ++i)
        #pragma unroll
        for (int j = 0; j < 4; ++j)
            #pragma unroll
            for (int e = 0; e < 4; ++e) acc[i][j][e] = 0.f;

    float4 xr[4];

    auto ldgA = [&](int kOff) {
        const float4* xp4 = reinterpret_cast<const float4*>(axp + kOff);
        #pragma unroll
        for (int i = 0; i < 4; ++i) xr[i] = xp4[i];
    };
    auto stsA = [&](int kOff, int buf) {
        const float4* rp4 = reinterpret_cast<const float4*>(srow + kOff);  // smem (bcast)
        const uint32_t aH = sb + buf * STG_STRIDE + OFF_AH;
        #pragma unroll
        for (int g = 0; g < 2; ++g) {
            const float4 xa = xr[2 * g], xb = xr[2 * g + 1];
            const float4 ra = rp4[2 * g], rb = rp4[2 * g + 1];
            uint32_t h[4], l[4];
            h[0] = bsplit2(xa.x * ra.x, xa.y * ra.y, l[0]);
            h[1] = bsplit2(xa.z * ra.z, xa.w * ra.w, l[1]);
            h[2] = bsplit2(xb.x * rb.x, xb.y * rb.y, l[2]);
            h[3] = bsplit2(xb.z * rb.z, xb.w * rb.w, l[3]);
            STS128(aH + sA[g], h[0], h[1], h[2], h[3]);
            STS128(aH + sA[g] + OFF_AL, l[0], l[1], l[2], l[3]);
        }
    };
    auto ldB = [&](int kOff, int buf) {
        const uint32_t bH = sb + buf * STG_STRIDE + OFF_BH;
        const char* gh = (const char*)g_wh4;
        const char* gl = (const char*)g_wl4;
        #pragma unroll
        for (int it = 0; it < 2; ++it) {
            const int idx = it * 512 + tid;          // 1024 16B-vectors
            const int ol = idx >> 3;
            const int kq = idx & 7;
            const size_t gb = ((size_t)(oBase + ol) * CIN + kOff + kq * 8) * 2;
            const uint32_t off = (uint32_t)(ol * 128) +
                                 (((uint32_t)(kq * 16)) ^ ((uint32_t)(ol & 7) * 16));
            CP16(bH + off, gh + gb);
            CP16(bH + off + 16384, gl + gb);
        }
    };
    auto compute = [&](int buf) {
        const uint32_t base = sb + buf * STG_STRIDE;
        #pragma unroll
        for (int kk = 0; kk < 4; ++kk) {
            const uint32_t kbl = (uint32_t)(kk * 32 + lkh * 16);
            uint32_t Ah[2][4], Al[2][4], Bh[2][4], Bl[2][4];
            #pragma unroll
            for (int mt = 0; mt < 2; ++mt) {
                const uint32_t ad = base + OFF_AH + aBase[mt] + (kbl ^ aXm[mt]);
                LDSM4(Ah[mt], ad);
                LDSM4(Al[mt], ad + OFF_AL);
            }
            #pragma unroll
            for (int nt = 0; nt < 2; ++nt) {
                const uint32_t bd = base + OFF_BH + bBase[nt] + (kbl ^ bXm[nt]);
                LDSM4(Bh[nt], bd);
                LDSM4(Bl[nt], bd + 16384);
            }
            // pass-major: 8 independent accumulators between reuses
            #pragma unroll
            for (int nt = 0; nt < 2; ++nt)
                #pragma unroll
                for (int mt = 0; mt < 2; ++mt) {
                    MMA16816(acc[mt][nt * 2],     Ah[mt], Bh[nt][0], Bh[nt][2]);
                    MMA16816(acc[mt][nt * 2 + 1], Ah[mt], Bh[nt][1], Bh[nt][3]);
                }
            #pragma unroll
            for (int nt = 0; nt < 2; ++nt)
                #pragma unroll
                for (int mt = 0; mt < 2; ++mt) {
                    MMA16816(acc[mt][nt * 2],     Al[mt], Bh[nt][0], Bh[nt][2]);
                    MMA16816(acc[mt][nt * 2 + 1], Al[mt], Bh[nt][1], Bh[nt][3]);
                }
            #pragma unroll
            for (int nt = 0; nt < 2; ++nt)
                #pragma unroll
                for (int mt = 0; mt < 2; ++mt) {
                    MMA16816(acc[mt][nt * 2],     Ah[mt], Bl[nt][0], Bl[nt][2]);
                    MMA16816(acc[mt][nt * 2 + 1], Ah[mt], Bl[nt][1], Bl[nt][3]);
                }
        }
    };

    // ---- prologue ----
    #pragma unroll
    for (int i = 0; i < 2; ++i) {
        const int e = i * 512 + tid;          // 768 = 2 x 384
        if (e < 768) {
            const int c = e - (e >= 384 ? 384 : 0);
            sr[e] = g_r[(size_t)(e >= 384 ? bt1 : bt0) * COUT + s * CIN + c];
        }
    }
    ldB(0, 0); CP_COMMIT();
    ldgA(0);
    __syncthreads();                          // sr visible before stsA reads it
    stsA(0, 0);
    ldgA(64);
    ldB(64, 1); CP_COMMIT();
    CP_WAIT1();
    __syncthreads();

    // ---- mainloop ----
    #pragma unroll 1
    for (int kc = 0; kc < 6; ++kc) {
        const int buf = kc & 1;
        if (kc < 5) {
            stsA((kc + 1) * 64, buf ^ 1);     // pure ALU+STS (r from smem)
            if (kc < 4) ldgA((kc + 2) * 64);  // LDG latency hidden under compute
        }
        compute(buf);
        if (kc < 5) {
            __syncthreads();                  // all warps done reading buf's B
            if (kc < 4) {
                ldB((kc + 2) * 64, buf); CP_COMMIT();
                CP_WAIT1();
            } else {
                CP_WAIT0();
            }
            __syncthreads();                  // cp.async data + stsA visible
        }
    }

    // ---- epilogue ----
    #pragma unroll
    for (int mt = 0; mt < 2; ++mt)
        #pragma unroll
        for (int rh = 0; rh < 2; ++rh) {
            const int m = mBase + wm + mt * 16 + (lane >> 2) + rh * 8;
            const int bt = m / NTOK;
            const int n = m - bt * NTOK;
            float* op = out + (size_t)bt * OUT_BT_STRIDE + n;
            const float* rr = g_r + (size_t)bt * COUT + oBase + wn;
            const float* bb = bias + oBase + wn;
            #pragma unroll
            for (int nt2 = 0; nt2 < 4; ++nt2) {
                const int c0 = nt2 * 8 + (lane & 3) * 2;
                const float v0 = acc[mt][nt2][rh * 2 + 0] + bb[c0] * rr[c0];
                const float v1 = acc[mt][nt2][rh * 2 + 1] + bb[c0 + 1] * rr[c0 + 1];
                op[(size_t)(oBase + wn + c0) * NTOK] = v0;
                op[(size_t)(oBase + wn + c0 + 1) * NTOK] = v1;
            }
        }
}

// ======================= launch =======================
extern "C" void kernel_launch(void* const* d_in, const int* in_sizes, int n_in,
                              void* d_out, int out_size) {
    const float* x = (const float*)d_in[0];
    const float* rf_w = (const float*)d_in[1];
    const float* rf_b = (const float*)d_in[2];
    const float* moe_w = (const float*)d_in[3];
    const float* moe_b = (const float*)d_in[4];
    const float* weight = (const float*)d_in[5];
    const float* bias = (const float*)d_in[6];
    float* out = (float*)d_out;

    cudaFuncSetAttribute(k_main, cudaFuncAttributeMaxDynamicSharedMemorySize, SMEM_MAIN);
    cudaFuncSetAttribute(k_routing, cudaFuncAttributeMaxDynamicSharedMemorySize, 61440);

    k_rf<<<32, 128>>>(x, rf_w, rf_b);
    k_wsplit<<<216, 256>>>(weight);
    k_routing<<<dim3(144, 8), 256, 61440>>>(x, moe_w, moe_b);
    k_main<<<dim3(9, 394), 512, SMEM_MAIN>>>(x, bias, out);
}